// round 13
// baseline (speedup 1.0000x reference)
#include <cuda_runtime.h>
#include <math.h>

static constexpr int BB = 8;
static constexpr int CC = 96;
static constexpr int C2 = 192;
static constexpr int C4 = 384;
static constexpr int NN = 3136;   // 56*56
static constexpr int KK = 9;
static constexpr float EPS_ = 1e-5f;

// ---------------- scratch (no allocations allowed) ----------------
__device__ float g_act[BB * CC * NN];
__device__ float g_t1 [BB * CC * NN];
__device__ float g_xf [BB * CC * NN];
__device__ float g_xn [BB * CC * NN];
__device__ float g_sq [BB * NN];
__device__ int   g_idx[BB * NN * KK];
__device__ float g_big[BB * C4 * NN];   // ffn hidden; also 2C y2 + 2C t3 for grapher

// ---------------- packed f32x2 helpers (FFMA2 via PTX) ----------------
typedef unsigned long long ull;
__device__ __forceinline__ ull pack2(float lo, float hi) {
    ull r;
    asm("mov.b64 %0, {%1, %2};" : "=l"(r) : "f"(lo), "f"(hi));
    return r;
}
__device__ __forceinline__ void ffma2(ull& d, ull a, ull b) {
    asm("fma.rn.f32x2 %0, %1, %2, %3;" : "=l"(d) : "l"(a), "l"(b), "l"(d));
}
__device__ __forceinline__ float2 unpack2(ull v) {
    float2 f;
    asm("mov.b64 {%0, %1}, %2;" : "=f"(f.x), "=f"(f.y) : "l"(v));
    return f;
}

// ---------------- 1x1 conv == batched GEMM: out[b,o,n] = sum_c W[o,c] X[b,c,n] + bias[o]
// 128 threads, 64x64 tile, thread = 4 o-rows x 8 n-cols (4 f32x2 pairs)
__global__ __launch_bounds__(128) void gemm_bias_kernel(
    const float* __restrict__ X, const float* __restrict__ W,
    const float* __restrict__ bias, float* __restrict__ out,
    int Cout, int Cin)
{
    int b  = blockIdx.z;
    int n0 = blockIdx.x * 64;
    int o0 = blockIdx.y * 64;
    int tid = threadIdx.x;
    int ty4 = (tid >> 3) * 4;   // 0..60 step 4
    int tx4 = (tid & 7) * 4;    // 0..28 step 4
    __shared__ float Ws[32][64];   // [k][o]
    __shared__ float Xs[32][64];   // [k][n]
    ull acc[4][4];
    #pragma unroll
    for (int i = 0; i < 4; i++)
        #pragma unroll
        for (int j = 0; j < 4; j++) acc[i][j] = 0ull;
    const float* Xb = X + (size_t)b * Cin * NN;

    for (int kt = 0; kt < Cin; kt += 32) {
        for (int t = tid; t < 512; t += 128) {
            int o = t & 63, kq = t >> 6;
            float4 w = make_float4(0.f, 0.f, 0.f, 0.f);
            if (o0 + o < Cout)
                w = *(const float4*)&W[(size_t)(o0 + o) * Cin + kt + kq * 4];
            Ws[kq * 4 + 0][o] = w.x;
            Ws[kq * 4 + 1][o] = w.y;
            Ws[kq * 4 + 2][o] = w.z;
            Ws[kq * 4 + 3][o] = w.w;
        }
        for (int t = tid; t < 512; t += 128) {
            int k = t >> 4, nq = t & 15;
            *(float4*)&Xs[k][nq * 4] =
                *(const float4*)&Xb[(size_t)(kt + k) * NN + n0 + nq * 4];
        }
        __syncthreads();
        #pragma unroll 8
        for (int k = 0; k < 32; k++) {
            float4 a = *(const float4*)&Ws[k][ty4];           // quarter-warp broadcast
            ulonglong2 bl = *(const ulonglong2*)&Xs[k][tx4];  // free f32x2 pairs
            ulonglong2 br = *(const ulonglong2*)&Xs[k][32 + tx4];
            ull bp[4] = {bl.x, bl.y, br.x, br.y};
            ull ap[4] = {pack2(a.x, a.x), pack2(a.y, a.y),
                         pack2(a.z, a.z), pack2(a.w, a.w)};
            #pragma unroll
            for (int i = 0; i < 4; i++)
                #pragma unroll
                for (int j = 0; j < 4; j++)
                    ffma2(acc[i][j], ap[i], bp[j]);
        }
        __syncthreads();
    }
    #pragma unroll
    for (int i = 0; i < 4; i++) {
        int o = o0 + ty4 + i;
        if (o < Cout) {
            float bvv = bias[o];
            float* op = out + ((size_t)b * Cout + o) * NN + n0;
            float2 p0 = unpack2(acc[i][0]), p1 = unpack2(acc[i][1]);
            float2 p2 = unpack2(acc[i][2]), p3 = unpack2(acc[i][3]);
            *(float4*)&op[tx4] =
                make_float4(p0.x + bvv, p0.y + bvv, p1.x + bvv, p1.y + bvv);
            *(float4*)&op[32 + tx4] =
                make_float4(p2.x + bvv, p2.y + bvv, p3.x + bvv, p3.y + bvv);
        }
    }
}

// ---------------- instance norm per (b,c) row over N; optional act + residual
// act: 0 none, 1 exact gelu, 2 relu
__global__ __launch_bounds__(256) void inorm_kernel(
    const float* __restrict__ in, float* __restrict__ out,
    const float* __restrict__ res, int act)
{
    int row = blockIdx.x;
    const float* p = in + (size_t)row * NN;
    int tid = threadIdx.x;
    float s = 0.f, s2 = 0.f;
    for (int i = tid; i < NN; i += 256) { float v = p[i]; s += v; s2 += v * v; }
    __shared__ float r0s[256], r1s[256];
    r0s[tid] = s; r1s[tid] = s2;
    __syncthreads();
    for (int st = 128; st > 0; st >>= 1) {
        if (tid < st) { r0s[tid] += r0s[tid + st]; r1s[tid] += r1s[tid + st]; }
        __syncthreads();
    }
    __shared__ float msh, rsh;
    if (tid == 0) {
        float mean = r0s[0] * (1.f / NN);
        float var  = r1s[0] * (1.f / NN) - mean * mean;
        msh = mean; rsh = rsqrtf(var + EPS_);
    }
    __syncthreads();
    float mean = msh, rstd = rsh;
    const float* rq = res ? res + (size_t)row * NN : nullptr;
    float* op = out + (size_t)row * NN;
    for (int i = tid; i < NN; i += 256) {
        float v = (p[i] - mean) * rstd;
        if (act == 1) v = 0.5f * v * (1.f + erff(v * 0.70710678118654752f));
        else if (act == 2) v = fmaxf(v, 0.f);
        if (rq) v += rq[i];
        op[i] = v;
    }
}

// ---------------- l2 normalize over channel dim per (b,n); also emit sq = ||xn||^2
__global__ __launch_bounds__(256) void l2norm_kernel(
    const float* __restrict__ xf, float* __restrict__ xn, float* __restrict__ sq)
{
    int t = blockIdx.x * 256 + threadIdx.x;
    if (t >= BB * NN) return;
    int b = t / NN, n = t - b * NN;
    const float* p = xf + (size_t)b * CC * NN + n;
    float s = 0.f;
    #pragma unroll 16
    for (int c = 0; c < CC; c++) { float v = p[(size_t)c * NN]; s += v * v; }
    float inv = 1.f / fmaxf(sqrtf(s), 1e-12f);
    float* q = xn + (size_t)b * CC * NN + n;
    #pragma unroll 16
    for (int c = 0; c < CC; c++) q[(size_t)c * NN] = p[(size_t)c * NN] * inv;
    sq[t] = s * inv * inv;
}

// ---------------- fused pairwise distance + top-9 smallest
// 256 threads, 64 n-rows per block; thread = 2 rows x 8 m-cols.
// Branchless register-resident sorted top-9 + per-row-per-tile batch filter:
// skip all 8 inserts when min(candidates) >= current 9th-best (strict-< safe).
__device__ __forceinline__ void ins9(float v, int m, float tv[KK], int ti[KK])
{
    bool c[KK];
    #pragma unroll
    for (int k = 0; k < KK; k++) c[k] = v < tv[k];
    tv[8] = c[8] ? (c[7] ? tv[7] : v) : tv[8];
    ti[8] = c[8] ? (c[7] ? ti[7] : m) : ti[8];
    #pragma unroll
    for (int k = 7; k >= 1; k--) {
        tv[k] = c[k - 1] ? tv[k - 1] : (c[k] ? v : tv[k]);
        ti[k] = c[k - 1] ? ti[k - 1] : (c[k] ? m : ti[k]);
    }
    tv[0] = c[0] ? v : tv[0];
    ti[0] = c[0] ? m : ti[0];
}

__global__ __launch_bounds__(256, 3) void dist_topk_kernel(
    const float* __restrict__ xn, const float* __restrict__ sq,
    const float* __restrict__ rp, int* __restrict__ oidx)
{
    __shared__ float smem_all[CC * 64 * 2];   // 48 KB
    float* Xn_s = smem_all;            // [c][64 n-rows]
    float* sh2  = smem_all + CC * 64;  // [c][64 m]; reused for merge

    int b = blockIdx.y;
    int n0 = blockIdx.x * 64;
    int tid = threadIdx.x;
    int g   = tid >> 3;          // 0..31 row group
    int mc4 = (tid & 7) * 4;     // 0..28 col group (two float4 halves)
    int r0 = g * 2, r1 = r0 + 1;

    const float* xb = xn + (size_t)b * CC * NN;
    for (int t = tid; t < CC * 16; t += 256) {
        int c = t >> 4, q = (t & 15) * 4;
        *(float4*)&Xn_s[c * 64 + q] = *(const float4*)&xb[(size_t)c * NN + n0 + q];
    }
    __syncthreads();

    float2 sqn2 = *(const float2*)&sq[b * NN + n0 + r0];
    float sqn0 = sqn2.x, sqn1 = sqn2.y;

    float tv0[KK], tv1[KK]; int ti0[KK], ti1[KK];
    #pragma unroll
    for (int k = 0; k < KK; k++) { tv0[k] = 1e30f; tv1[k] = 1e30f; ti0[k] = 0; ti1[k] = 0; }

    for (int m0 = 0; m0 < NN; m0 += 64) {
        __syncthreads();
        for (int t = tid; t < CC * 16; t += 256) {
            int c = t >> 4, q = (t & 15) * 4;
            *(float4*)&sh2[c * 64 + q] = *(const float4*)&xb[(size_t)c * NN + m0 + q];
        }
        __syncthreads();
        ull acc0[4], acc1[4];
        #pragma unroll
        for (int j = 0; j < 4; j++) { acc0[j] = 0ull; acc1[j] = 0ull; }
        #pragma unroll 8
        for (int c = 0; c < CC; c++) {
            float2 a = *(const float2*)&Xn_s[c * 64 + r0];              // broadcast
            ulonglong2 blp = *(const ulonglong2*)&sh2[c * 64 + mc4];    // free pairs
            ulonglong2 brp = *(const ulonglong2*)&sh2[c * 64 + 32 + mc4];
            ull bp[4] = {blp.x, blp.y, brp.x, brp.y};
            ull a0 = pack2(a.x, a.x), a1 = pack2(a.y, a.y);
            #pragma unroll
            for (int j = 0; j < 4; j++) {
                ffma2(acc0[j], a0, bp[j]);
                ffma2(acc1[j], a1, bp[j]);
            }
        }
        // epilogue: dist + batch-filtered branchless topk insert
        const float* sqm = sq + b * NN + m0;
        float4 sqL = *(const float4*)&sqm[mc4];
        float4 sqR = *(const float4*)&sqm[32 + mc4];
        float sv[8] = {sqL.x, sqL.y, sqL.z, sqL.w, sqR.x, sqR.y, sqR.z, sqR.w};
        const float* rpr0 = rp + (size_t)(n0 + r0) * NN + m0;
        const float* rpr1 = rp + (size_t)(n0 + r1) * NN + m0;
        float4 rp0L = *(const float4*)&rpr0[mc4];
        float4 rp0R = *(const float4*)&rpr0[32 + mc4];
        float4 rp1L = *(const float4*)&rpr1[mc4];
        float4 rp1R = *(const float4*)&rpr1[32 + mc4];
        float r0v[8] = {rp0L.x, rp0L.y, rp0L.z, rp0L.w, rp0R.x, rp0R.y, rp0R.z, rp0R.w};
        float r1v[8] = {rp1L.x, rp1L.y, rp1L.z, rp1L.w, rp1R.x, rp1R.y, rp1R.z, rp1R.w};
        float2 p00 = unpack2(acc0[0]), p01 = unpack2(acc0[1]);
        float2 p02 = unpack2(acc0[2]), p03 = unpack2(acc0[3]);
        float2 p10 = unpack2(acc1[0]), p11 = unpack2(acc1[1]);
        float2 p12 = unpack2(acc1[2]), p13 = unpack2(acc1[3]);
        float dot0[8] = {p00.x, p00.y, p01.x, p01.y, p02.x, p02.y, p03.x, p03.y};
        float dot1[8] = {p10.x, p10.y, p11.x, p11.y, p12.x, p12.y, p13.x, p13.y};
        float d0[8], d1[8];
        #pragma unroll
        for (int j = 0; j < 8; j++) {
            d0[j] = fmaf(-2.f, dot0[j], sqn0 + sv[j] + r0v[j]);
            d1[j] = fmaf(-2.f, dot1[j], sqn1 + sv[j] + r1v[j]);
        }
        float mn0 = fminf(fminf(fminf(d0[0], d0[1]), fminf(d0[2], d0[3])),
                          fminf(fminf(d0[4], d0[5]), fminf(d0[6], d0[7])));
        float mn1 = fminf(fminf(fminf(d1[0], d1[1]), fminf(d1[2], d1[3])),
                          fminf(fminf(d1[4], d1[5]), fminf(d1[6], d1[7])));
        if (mn0 < tv0[8]) {
            #pragma unroll
            for (int j = 0; j < 8; j++) {
                int m = m0 + (j < 4 ? mc4 + j : 32 + mc4 + (j - 4));
                ins9(d0[j], m, tv0, ti0);
            }
        }
        if (mn1 < tv1[8]) {
            #pragma unroll
            for (int j = 0; j < 8; j++) {
                int m = m0 + (j < 4 ? mc4 + j : 32 + mc4 + (j - 4));
                ins9(d1[j], m, tv1, ti1);
            }
        }
    }

    // ---------- merge: 8 sorted partial lists per row, single pass ----------
    __syncthreads();
    float* cv = smem_all;                        // [64][8][9] values (4608 f)
    int*   ci = (int*)(smem_all + 64 * 8 * KK);  // [64][8][9] indices
    int cg = tid & 7;
    #pragma unroll
    for (int k = 0; k < KK; k++) {
        cv[(r0 * 8 + cg) * KK + k] = tv0[k]; ci[(r0 * 8 + cg) * KK + k] = ti0[k];
        cv[(r1 * 8 + cg) * KK + k] = tv1[k]; ci[(r1 * 8 + cg) * KK + k] = ti1[k];
    }
    __syncthreads();
    if (tid < 64) {
        float* rv = cv + tid * 8 * KK;
        int*   ri = ci + tid * 8 * KK;
        int* op = oidx + ((size_t)b * NN + n0 + tid) * KK;
        for (int k = 0; k < KK; k++) {
            float best = 2e30f; int bi = 0, bt = 0;
            for (int t = 0; t < 8 * KK; t++) {
                float v = rv[t];
                if (v < best) { best = v; bi = ri[t]; bt = t; }
            }
            rv[bt] = 3e30f;   // consume
            op[k] = bi;
        }
    }
}

// ---------------- gather neighbors, max(x_j - x_i), write channel-interleaved (B,2C,N)
__global__ __launch_bounds__(256) void aggregate_kernel(
    const float* __restrict__ xf, const int* __restrict__ idx, float* __restrict__ y)
{
    int bc = blockIdx.x;            // b*CC + c
    __shared__ float row[NN];
    const float* p = xf + (size_t)bc * NN;
    for (int i = threadIdx.x; i < NN; i += 256) row[i] = p[i];
    __syncthreads();
    int b = bc / CC, c = bc - b * CC;
    const int* ip = idx + (size_t)b * NN * KK;
    float* y0 = y + ((size_t)b * C2 + 2 * c) * NN;
    float* y1 = y0 + NN;
    for (int n = threadIdx.x; n < NN; n += 256) {
        float xi = row[n];
        float mx = -3e38f;
        #pragma unroll
        for (int k = 0; k < KK; k++) {
            int j = ip[n * KK + k];
            mx = fmaxf(mx, row[j] - xi);
        }
        y0[n] = xi;
        y1[n] = mx;
    }
}

// ---------------- host orchestration ----------------
static void run_conv(const float* X, const float* W, const float* bias,
                     float* out, int Cout, int Cin)
{
    dim3 g(NN / 64, (Cout + 63) / 64, BB);
    gemm_bias_kernel<<<g, 128>>>(X, W, bias, out, Cout, Cin);
}
static void run_inorm(const float* in, float* out, const float* res, int Crows, int act)
{
    inorm_kernel<<<BB * Crows, 256>>>(in, out, res, act);
}

extern "C" void kernel_launch(void* const* d_in, const int* in_sizes, int n_in,
                              void* d_out, int out_size)
{
    (void)in_sizes; (void)n_in; (void)out_size;
    const float* x  = (const float*)d_in[0];
    const float* rp = (const float*)d_in[1];
    const float* P[20];
    for (int i = 0; i < 20; i++) P[i] = (const float*)d_in[2 + i];

    float *act, *t1, *xf, *xnp, *sqp, *big; int* idxp;
    cudaGetSymbolAddress((void**)&act,  g_act);
    cudaGetSymbolAddress((void**)&t1,   g_t1);
    cudaGetSymbolAddress((void**)&xf,   g_xf);
    cudaGetSymbolAddress((void**)&xnp,  g_xn);
    cudaGetSymbolAddress((void**)&sqp,  g_sq);
    cudaGetSymbolAddress((void**)&idxp, g_idx);
    cudaGetSymbolAddress((void**)&big,  g_big);
    float* y2 = big;                          // (B,2C,N)
    float* t3 = big + (size_t)BB * C2 * NN;   // (B,2C,N)
    float* out = (float*)d_out;

    auto grapher = [&](const float* inx,
                       const float* w1, const float* b1,
                       const float* mw, const float* mb,
                       const float* w2, const float* b2, float* outp) {
        run_conv(inx, w1, b1, t1, CC, CC);
        run_inorm(t1, xf, nullptr, CC, 0);                          // xf
        l2norm_kernel<<<(BB * NN + 255) / 256, 256>>>(xf, xnp, sqp);
        dim3 dg(NN / 64, BB);
        dist_topk_kernel<<<dg, 256>>>(xnp, sqp, rp, idxp);
        aggregate_kernel<<<BB * CC, 256>>>(xf, idxp, y2);           // (B,2C,N)
        run_conv(y2, mw, mb, t3, C2, C2);
        run_inorm(t3, t3, nullptr, C2, 1);                          // gelu, in-place
        run_conv(t3, w2, b2, t1, CC, C2);
        run_inorm(t1, outp, inx, CC, 0);                            // + shortcut
    };
    auto ffn = [&](float* a, const float* w1, const float* b1,
                   const float* w2, const float* b2) {
        run_conv(a, w1, b1, big, C4, CC);
        run_inorm(big, big, nullptr, C4, 1);                        // gelu, in-place
        run_conv(big, w2, b2, t1, CC, C4);
        run_inorm(t1, a, a, CC, 0);                                 // + shortcut
    };

    grapher(x, P[0], P[1], P[2], P[3], P[4], P[5], act);
    ffn(act, P[12], P[13], P[14], P[15]);
    run_inorm(act, act, nullptr, CC, 2);                            // relu(inorm)
    grapher(act, P[6], P[7], P[8], P[9], P[10], P[11], act);
    ffn(act, P[16], P[17], P[18], P[19]);
    run_inorm(act, out, x, CC, 0);                                  // x + inorm(y)
}

// round 14
// speedup vs baseline: 1.1036x; 1.1036x over previous
#include <cuda_runtime.h>
#include <math.h>

static constexpr int BB = 8;
static constexpr int CC = 96;
static constexpr int C2 = 192;
static constexpr int C4 = 384;
static constexpr int NN = 3136;   // 56*56
static constexpr int KK = 9;
static constexpr float EPS_ = 1e-5f;

// ---------------- scratch (no allocations allowed) ----------------
__device__ float g_act[BB * CC * NN];
__device__ float g_t1 [BB * CC * NN];
__device__ float g_xf [BB * CC * NN];
__device__ float g_xn [BB * CC * NN];
__device__ float g_sq [BB * NN];
__device__ int   g_idx[BB * NN * KK];
__device__ float g_big[BB * C4 * NN];   // ffn hidden; also 2C y2 + 2C t3 for grapher

// ---------------- packed f32x2 helpers (FFMA2 via PTX) ----------------
typedef unsigned long long ull;
__device__ __forceinline__ ull pack2(float lo, float hi) {
    ull r;
    asm("mov.b64 %0, {%1, %2};" : "=l"(r) : "f"(lo), "f"(hi));
    return r;
}
__device__ __forceinline__ void ffma2(ull& d, ull a, ull b) {
    asm("fma.rn.f32x2 %0, %1, %2, %3;" : "=l"(d) : "l"(a), "l"(b), "l"(d));
}
__device__ __forceinline__ float2 unpack2(ull v) {
    float2 f;
    asm("mov.b64 {%0, %1}, %2;" : "=f"(f.x), "=f"(f.y) : "l"(v));
    return f;
}

// ---------------- 1x1 conv == batched GEMM: out[b,o,n] = sum_c W[o,c] X[b,c,n] + bias[o]
// 128 threads, 64x64 tile, thread = 4 o-rows x 8 n-cols (4 f32x2 pairs)
__global__ __launch_bounds__(128) void gemm_bias_kernel(
    const float* __restrict__ X, const float* __restrict__ W,
    const float* __restrict__ bias, float* __restrict__ out,
    int Cout, int Cin)
{
    int b  = blockIdx.z;
    int n0 = blockIdx.x * 64;
    int o0 = blockIdx.y * 64;
    int tid = threadIdx.x;
    int ty4 = (tid >> 3) * 4;   // 0..60 step 4
    int tx4 = (tid & 7) * 4;    // 0..28 step 4
    __shared__ float Ws[32][64];   // [k][o]
    __shared__ float Xs[32][64];   // [k][n]
    ull acc[4][4];
    #pragma unroll
    for (int i = 0; i < 4; i++)
        #pragma unroll
        for (int j = 0; j < 4; j++) acc[i][j] = 0ull;
    const float* Xb = X + (size_t)b * Cin * NN;

    for (int kt = 0; kt < Cin; kt += 32) {
        for (int t = tid; t < 512; t += 128) {
            int o = t & 63, kq = t >> 6;
            float4 w = make_float4(0.f, 0.f, 0.f, 0.f);
            if (o0 + o < Cout)
                w = *(const float4*)&W[(size_t)(o0 + o) * Cin + kt + kq * 4];
            Ws[kq * 4 + 0][o] = w.x;
            Ws[kq * 4 + 1][o] = w.y;
            Ws[kq * 4 + 2][o] = w.z;
            Ws[kq * 4 + 3][o] = w.w;
        }
        for (int t = tid; t < 512; t += 128) {
            int k = t >> 4, nq = t & 15;
            *(float4*)&Xs[k][nq * 4] =
                *(const float4*)&Xb[(size_t)(kt + k) * NN + n0 + nq * 4];
        }
        __syncthreads();
        #pragma unroll 8
        for (int k = 0; k < 32; k++) {
            float4 a = *(const float4*)&Ws[k][ty4];           // quarter-warp broadcast
            ulonglong2 bl = *(const ulonglong2*)&Xs[k][tx4];  // free f32x2 pairs
            ulonglong2 br = *(const ulonglong2*)&Xs[k][32 + tx4];
            ull bp[4] = {bl.x, bl.y, br.x, br.y};
            ull ap[4] = {pack2(a.x, a.x), pack2(a.y, a.y),
                         pack2(a.z, a.z), pack2(a.w, a.w)};
            #pragma unroll
            for (int i = 0; i < 4; i++)
                #pragma unroll
                for (int j = 0; j < 4; j++)
                    ffma2(acc[i][j], ap[i], bp[j]);
        }
        __syncthreads();
    }
    #pragma unroll
    for (int i = 0; i < 4; i++) {
        int o = o0 + ty4 + i;
        if (o < Cout) {
            float bvv = bias[o];
            float* op = out + ((size_t)b * Cout + o) * NN + n0;
            float2 p0 = unpack2(acc[i][0]), p1 = unpack2(acc[i][1]);
            float2 p2 = unpack2(acc[i][2]), p3 = unpack2(acc[i][3]);
            *(float4*)&op[tx4] =
                make_float4(p0.x + bvv, p0.y + bvv, p1.x + bvv, p1.y + bvv);
            *(float4*)&op[32 + tx4] =
                make_float4(p2.x + bvv, p2.y + bvv, p3.x + bvv, p3.y + bvv);
        }
    }
}

// ---------------- instance norm per (b,c) row over N; optional act + residual
// act: 0 none, 1 exact gelu, 2 relu
__global__ __launch_bounds__(256) void inorm_kernel(
    const float* __restrict__ in, float* __restrict__ out,
    const float* __restrict__ res, int act)
{
    int row = blockIdx.x;
    const float* p = in + (size_t)row * NN;
    int tid = threadIdx.x;
    float s = 0.f, s2 = 0.f;
    for (int i = tid; i < NN; i += 256) { float v = p[i]; s += v; s2 += v * v; }
    __shared__ float r0s[256], r1s[256];
    r0s[tid] = s; r1s[tid] = s2;
    __syncthreads();
    for (int st = 128; st > 0; st >>= 1) {
        if (tid < st) { r0s[tid] += r0s[tid + st]; r1s[tid] += r1s[tid + st]; }
        __syncthreads();
    }
    __shared__ float msh, rsh;
    if (tid == 0) {
        float mean = r0s[0] * (1.f / NN);
        float var  = r1s[0] * (1.f / NN) - mean * mean;
        msh = mean; rsh = rsqrtf(var + EPS_);
    }
    __syncthreads();
    float mean = msh, rstd = rsh;
    const float* rq = res ? res + (size_t)row * NN : nullptr;
    float* op = out + (size_t)row * NN;
    for (int i = tid; i < NN; i += 256) {
        float v = (p[i] - mean) * rstd;
        if (act == 1) v = 0.5f * v * (1.f + erff(v * 0.70710678118654752f));
        else if (act == 2) v = fmaxf(v, 0.f);
        if (rq) v += rq[i];
        op[i] = v;
    }
}

// ---------------- l2 normalize over channel dim per (b,n); also emit sq = ||xn||^2
__global__ __launch_bounds__(256) void l2norm_kernel(
    const float* __restrict__ xf, float* __restrict__ xn, float* __restrict__ sq)
{
    int t = blockIdx.x * 256 + threadIdx.x;
    if (t >= BB * NN) return;
    int b = t / NN, n = t - b * NN;
    const float* p = xf + (size_t)b * CC * NN + n;
    float s = 0.f;
    #pragma unroll 16
    for (int c = 0; c < CC; c++) { float v = p[(size_t)c * NN]; s += v * v; }
    float inv = 1.f / fmaxf(sqrtf(s), 1e-12f);
    float* q = xn + (size_t)b * CC * NN + n;
    #pragma unroll 16
    for (int c = 0; c < CC; c++) q[(size_t)c * NN] = p[(size_t)c * NN] * inv;
    sq[t] = s * inv * inv;
}

// ---------------- fused pairwise distance + top-9 smallest
// 256 threads, 64 n-rows per block; thread = 2 rows x 8 m-cols.
// m-tiles of 128 (two 64-col halves per barrier period) to amortize
// load-barrier latency. Branchless register-resident sorted top-9.
__device__ __forceinline__ void ins9(float v, int m, float tv[KK], int ti[KK])
{
    bool c[KK];
    #pragma unroll
    for (int k = 0; k < KK; k++) c[k] = v < tv[k];
    tv[8] = c[8] ? (c[7] ? tv[7] : v) : tv[8];
    ti[8] = c[8] ? (c[7] ? ti[7] : m) : ti[8];
    #pragma unroll
    for (int k = 7; k >= 1; k--) {
        tv[k] = c[k - 1] ? tv[k - 1] : (c[k] ? v : tv[k]);
        ti[k] = c[k - 1] ? ti[k - 1] : (c[k] ? m : ti[k]);
    }
    tv[0] = c[0] ? v : tv[0];
    ti[0] = c[0] ? m : ti[0];
}

__global__ __launch_bounds__(256, 3) void dist_topk_kernel(
    const float* __restrict__ xn, const float* __restrict__ sq,
    const float* __restrict__ rp, int* __restrict__ oidx)
{
    extern __shared__ float dsm[];
    float* Xn_s = dsm;             // [c][64 n-rows]   24 KB
    float* sh2  = dsm + CC * 64;   // [c][128 m-cols]  48 KB; reused for merge

    int b = blockIdx.y;
    int n0 = blockIdx.x * 64;
    int tid = threadIdx.x;
    int g   = tid >> 3;          // 0..31 row group
    int mc4 = (tid & 7) * 4;     // 0..28 col group (two float4 halves)
    int r0 = g * 2, r1 = r0 + 1;

    const float* xb = xn + (size_t)b * CC * NN;
    for (int t = tid; t < CC * 16; t += 256) {
        int c = t >> 4, q = (t & 15) * 4;
        *(float4*)&Xn_s[c * 64 + q] = *(const float4*)&xb[(size_t)c * NN + n0 + q];
    }
    __syncthreads();

    float2 sqn2 = *(const float2*)&sq[b * NN + n0 + r0];
    float sqn0 = sqn2.x, sqn1 = sqn2.y;

    float tv0[KK], tv1[KK]; int ti0[KK], ti1[KK];
    #pragma unroll
    for (int k = 0; k < KK; k++) { tv0[k] = 1e30f; tv1[k] = 1e30f; ti0[k] = 0; ti1[k] = 0; }

    for (int m0 = 0; m0 < NN; m0 += 128) {
        __syncthreads();
        if (m0 + 128 <= NN) {
            for (int t = tid; t < CC * 32; t += 256) {
                int c = t >> 5, q = (t & 31) * 4;
                *(float4*)&sh2[c * 128 + q] =
                    *(const float4*)&xb[(size_t)c * NN + m0 + q];
            }
        } else {
            for (int t = tid; t < CC * 16; t += 256) {
                int c = t >> 4, q = (t & 15) * 4;
                *(float4*)&sh2[c * 128 + q] =
                    *(const float4*)&xb[(size_t)c * NN + m0 + q];
            }
        }
        __syncthreads();
        #pragma unroll 1
        for (int h = 0; h < 2; h++) {
            int m0h = m0 + h * 64;
            if (m0h >= NN) break;
            const float* sb = sh2 + h * 64;
            ull acc0[4], acc1[4];
            #pragma unroll
            for (int j = 0; j < 4; j++) { acc0[j] = 0ull; acc1[j] = 0ull; }
            #pragma unroll 8
            for (int c = 0; c < CC; c++) {
                float2 a = *(const float2*)&Xn_s[c * 64 + r0];            // broadcast
                ulonglong2 blp = *(const ulonglong2*)&sb[c * 128 + mc4];  // free pairs
                ulonglong2 brp = *(const ulonglong2*)&sb[c * 128 + 32 + mc4];
                ull bp[4] = {blp.x, blp.y, brp.x, brp.y};
                ull a0 = pack2(a.x, a.x), a1 = pack2(a.y, a.y);
                #pragma unroll
                for (int j = 0; j < 4; j++) {
                    ffma2(acc0[j], a0, bp[j]);
                    ffma2(acc1[j], a1, bp[j]);
                }
            }
            // epilogue: dist + branchless topk insert (16B-aligned vector loads)
            const float* sqm = sq + b * NN + m0h;
            float4 sqL = *(const float4*)&sqm[mc4];
            float4 sqR = *(const float4*)&sqm[32 + mc4];
            float sv[8] = {sqL.x, sqL.y, sqL.z, sqL.w, sqR.x, sqR.y, sqR.z, sqR.w};
            const float* rpr0 = rp + (size_t)(n0 + r0) * NN + m0h;
            const float* rpr1 = rp + (size_t)(n0 + r1) * NN + m0h;
            float4 rp0L = *(const float4*)&rpr0[mc4];
            float4 rp0R = *(const float4*)&rpr0[32 + mc4];
            float4 rp1L = *(const float4*)&rpr1[mc4];
            float4 rp1R = *(const float4*)&rpr1[32 + mc4];
            float r0v[8] = {rp0L.x, rp0L.y, rp0L.z, rp0L.w,
                            rp0R.x, rp0R.y, rp0R.z, rp0R.w};
            float r1v[8] = {rp1L.x, rp1L.y, rp1L.z, rp1L.w,
                            rp1R.x, rp1R.y, rp1R.z, rp1R.w};
            float2 p00 = unpack2(acc0[0]), p01 = unpack2(acc0[1]);
            float2 p02 = unpack2(acc0[2]), p03 = unpack2(acc0[3]);
            float2 p10 = unpack2(acc1[0]), p11 = unpack2(acc1[1]);
            float2 p12 = unpack2(acc1[2]), p13 = unpack2(acc1[3]);
            float dot0[8] = {p00.x, p00.y, p01.x, p01.y, p02.x, p02.y, p03.x, p03.y};
            float dot1[8] = {p10.x, p10.y, p11.x, p11.y, p12.x, p12.y, p13.x, p13.y};
            #pragma unroll
            for (int j = 0; j < 8; j++) {
                int m = m0h + (j < 4 ? mc4 + j : 32 + mc4 + (j - 4));
                float d0 = fmaf(-2.f, dot0[j], sqn0 + sv[j] + r0v[j]);
                float d1 = fmaf(-2.f, dot1[j], sqn1 + sv[j] + r1v[j]);
                ins9(d0, m, tv0, ti0);
                ins9(d1, m, tv1, ti1);
            }
        }
    }

    // ---------- merge: 8 sorted partial lists per row, single pass ----------
    __syncthreads();
    float* cv = dsm;                        // [64][8][9] values (4608 f)
    int*   ci = (int*)(dsm + 64 * 8 * KK);  // [64][8][9] indices
    int cg = tid & 7;
    #pragma unroll
    for (int k = 0; k < KK; k++) {
        cv[(r0 * 8 + cg) * KK + k] = tv0[k]; ci[(r0 * 8 + cg) * KK + k] = ti0[k];
        cv[(r1 * 8 + cg) * KK + k] = tv1[k]; ci[(r1 * 8 + cg) * KK + k] = ti1[k];
    }
    __syncthreads();
    if (tid < 64) {
        float* rv = cv + tid * 8 * KK;
        int*   ri = ci + tid * 8 * KK;
        int* op = oidx + ((size_t)b * NN + n0 + tid) * KK;
        for (int k = 0; k < KK; k++) {
            float best = 2e30f; int bi = 0, bt = 0;
            for (int t = 0; t < 8 * KK; t++) {
                float v = rv[t];
                if (v < best) { best = v; bi = ri[t]; bt = t; }
            }
            rv[bt] = 3e30f;   // consume
            op[k] = bi;
        }
    }
}

// ---------------- gather neighbors, max(x_j - x_i), write channel-interleaved (B,2C,N)
__global__ __launch_bounds__(256) void aggregate_kernel(
    const float* __restrict__ xf, const int* __restrict__ idx, float* __restrict__ y)
{
    int bc = blockIdx.x;            // b*CC + c
    __shared__ float row[NN];
    const float* p = xf + (size_t)bc * NN;
    for (int i = threadIdx.x; i < NN; i += 256) row[i] = p[i];
    __syncthreads();
    int b = bc / CC, c = bc - b * CC;
    const int* ip = idx + (size_t)b * NN * KK;
    float* y0 = y + ((size_t)b * C2 + 2 * c) * NN;
    float* y1 = y0 + NN;
    for (int n = threadIdx.x; n < NN; n += 256) {
        float xi = row[n];
        float mx = -3e38f;
        #pragma unroll
        for (int k = 0; k < KK; k++) {
            int j = ip[n * KK + k];
            mx = fmaxf(mx, row[j] - xi);
        }
        y0[n] = xi;
        y1[n] = mx;
    }
}

// ---------------- host orchestration ----------------
static constexpr int DIST_SMEM = CC * 192 * (int)sizeof(float);   // 73728 B

static void run_conv(const float* X, const float* W, const float* bias,
                     float* out, int Cout, int Cin)
{
    dim3 g(NN / 64, (Cout + 63) / 64, BB);
    gemm_bias_kernel<<<g, 128>>>(X, W, bias, out, Cout, Cin);
}
static void run_inorm(const float* in, float* out, const float* res, int Crows, int act)
{
    inorm_kernel<<<BB * Crows, 256>>>(in, out, res, act);
}

extern "C" void kernel_launch(void* const* d_in, const int* in_sizes, int n_in,
                              void* d_out, int out_size)
{
    (void)in_sizes; (void)n_in; (void)out_size;
    const float* x  = (const float*)d_in[0];
    const float* rp = (const float*)d_in[1];
    const float* P[20];
    for (int i = 0; i < 20; i++) P[i] = (const float*)d_in[2 + i];

    cudaFuncSetAttribute(dist_topk_kernel,
                         cudaFuncAttributeMaxDynamicSharedMemorySize, DIST_SMEM);

    float *act, *t1, *xf, *xnp, *sqp, *big; int* idxp;
    cudaGetSymbolAddress((void**)&act,  g_act);
    cudaGetSymbolAddress((void**)&t1,   g_t1);
    cudaGetSymbolAddress((void**)&xf,   g_xf);
    cudaGetSymbolAddress((void**)&xnp,  g_xn);
    cudaGetSymbolAddress((void**)&sqp,  g_sq);
    cudaGetSymbolAddress((void**)&idxp, g_idx);
    cudaGetSymbolAddress((void**)&big,  g_big);
    float* y2 = big;                          // (B,2C,N)
    float* t3 = big + (size_t)BB * C2 * NN;   // (B,2C,N)
    float* out = (float*)d_out;

    auto grapher = [&](const float* inx,
                       const float* w1, const float* b1,
                       const float* mw, const float* mb,
                       const float* w2, const float* b2, float* outp) {
        run_conv(inx, w1, b1, t1, CC, CC);
        run_inorm(t1, xf, nullptr, CC, 0);                          // xf
        l2norm_kernel<<<(BB * NN + 255) / 256, 256>>>(xf, xnp, sqp);
        dim3 dg(NN / 64, BB);
        dist_topk_kernel<<<dg, 256, DIST_SMEM>>>(xnp, sqp, rp, idxp);
        aggregate_kernel<<<BB * CC, 256>>>(xf, idxp, y2);           // (B,2C,N)
        run_conv(y2, mw, mb, t3, C2, C2);
        run_inorm(t3, t3, nullptr, C2, 1);                          // gelu, in-place
        run_conv(t3, w2, b2, t1, CC, C2);
        run_inorm(t1, outp, inx, CC, 0);                            // + shortcut
    };
    auto ffn = [&](float* a, const float* w1, const float* b1,
                   const float* w2, const float* b2) {
        run_conv(a, w1, b1, big, C4, CC);
        run_inorm(big, big, nullptr, C4, 1);                        // gelu, in-place
        run_conv(big, w2, b2, t1, CC, C4);
        run_inorm(t1, a, a, CC, 0);                                 // + shortcut
    };

    grapher(x, P[0], P[1], P[2], P[3], P[4], P[5], act);
    ffn(act, P[12], P[13], P[14], P[15]);
    run_inorm(act, act, nullptr, CC, 2);                            // relu(inorm)
    grapher(act, P[6], P[7], P[8], P[9], P[10], P[11], act);
    ffn(act, P[16], P[17], P[18], P[19]);
    run_inorm(act, out, x, CC, 0);                                  // x + inorm(y)
}

// round 15
// speedup vs baseline: 1.1404x; 1.0333x over previous
#include <cuda_runtime.h>
#include <math.h>

static constexpr int BB = 8;
static constexpr int CC = 96;
static constexpr int C2 = 192;
static constexpr int C4 = 384;
static constexpr int NN = 3136;   // 56*56
static constexpr int KK = 9;
static constexpr float EPS_ = 1e-5f;

// ---------------- scratch (no allocations allowed) ----------------
__device__ float g_act[BB * CC * NN];
__device__ float g_t1 [BB * CC * NN];
__device__ float g_xf [BB * CC * NN];
__device__ float g_xn [BB * CC * NN];
__device__ float g_sq [BB * NN];
__device__ int   g_idx[BB * NN * KK];
__device__ float g_big[BB * C4 * NN];   // ffn hidden; also 2C y2 + 2C t3 for grapher

// ---------------- packed f32x2 helpers (FFMA2 via PTX) ----------------
typedef unsigned long long ull;
__device__ __forceinline__ ull pack2(float lo, float hi) {
    ull r;
    asm("mov.b64 %0, {%1, %2};" : "=l"(r) : "f"(lo), "f"(hi));
    return r;
}
__device__ __forceinline__ void ffma2(ull& d, ull a, ull b) {
    asm("fma.rn.f32x2 %0, %1, %2, %3;" : "=l"(d) : "l"(a), "l"(b), "l"(d));
}
__device__ __forceinline__ float2 unpack2(ull v) {
    float2 f;
    asm("mov.b64 {%0, %1}, %2;" : "=f"(f.x), "=f"(f.y) : "l"(v));
    return f;
}

// ---------------- 1x1 conv == batched GEMM: out[b,o,n] = sum_c W[o,c] X[b,c,n] + bias[o]
// 128 threads, 64x64 tile, thread = 4 o-rows x 8 n-cols (4 f32x2 pairs)
// K-chunk = 96 (one barrier pair per 96 k-steps; Cin is always a multiple of 96)
__global__ __launch_bounds__(128) void gemm_bias_kernel(
    const float* __restrict__ X, const float* __restrict__ W,
    const float* __restrict__ bias, float* __restrict__ out,
    int Cout, int Cin)
{
    int b  = blockIdx.z;
    int n0 = blockIdx.x * 64;
    int o0 = blockIdx.y * 64;
    int tid = threadIdx.x;
    int ty4 = (tid >> 3) * 4;   // 0..60 step 4
    int tx4 = (tid & 7) * 4;    // 0..28 step 4
    __shared__ float Ws[96][64];   // [k][o]  24 KB
    __shared__ float Xs[96][64];   // [k][n]  24 KB
    ull acc[4][4];
    #pragma unroll
    for (int i = 0; i < 4; i++)
        #pragma unroll
        for (int j = 0; j < 4; j++) acc[i][j] = 0ull;
    const float* Xb = X + (size_t)b * Cin * NN;

    for (int kt = 0; kt < Cin; kt += 96) {
        // load W chunk: 64 o-rows x 96 k (24 float4 per o-row)
        for (int t = tid; t < 1536; t += 128) {
            int kq = t >> 6, o = t & 63;          // kq 0..23
            float4 w = make_float4(0.f, 0.f, 0.f, 0.f);
            if (o0 + o < Cout)
                w = *(const float4*)&W[(size_t)(o0 + o) * Cin + kt + kq * 4];
            Ws[kq * 4 + 0][o] = w.x;
            Ws[kq * 4 + 1][o] = w.y;
            Ws[kq * 4 + 2][o] = w.z;
            Ws[kq * 4 + 3][o] = w.w;
        }
        // load X chunk: 96 k-rows x 64 n (16 float4 per k-row)
        for (int t = tid; t < 1536; t += 128) {
            int k = t >> 4, nq = t & 15;
            *(float4*)&Xs[k][nq * 4] =
                *(const float4*)&Xb[(size_t)(kt + k) * NN + n0 + nq * 4];
        }
        __syncthreads();
        #pragma unroll 8
        for (int k = 0; k < 96; k++) {
            float4 a = *(const float4*)&Ws[k][ty4];           // quarter-warp broadcast
            ulonglong2 bl = *(const ulonglong2*)&Xs[k][tx4];  // free f32x2 pairs
            ulonglong2 br = *(const ulonglong2*)&Xs[k][32 + tx4];
            ull bp[4] = {bl.x, bl.y, br.x, br.y};
            ull ap[4] = {pack2(a.x, a.x), pack2(a.y, a.y),
                         pack2(a.z, a.z), pack2(a.w, a.w)};
            #pragma unroll
            for (int i = 0; i < 4; i++)
                #pragma unroll
                for (int j = 0; j < 4; j++)
                    ffma2(acc[i][j], ap[i], bp[j]);
        }
        __syncthreads();
    }
    #pragma unroll
    for (int i = 0; i < 4; i++) {
        int o = o0 + ty4 + i;
        if (o < Cout) {
            float bvv = bias[o];
            float* op = out + ((size_t)b * Cout + o) * NN + n0;
            float2 p0 = unpack2(acc[i][0]), p1 = unpack2(acc[i][1]);
            float2 p2 = unpack2(acc[i][2]), p3 = unpack2(acc[i][3]);
            *(float4*)&op[tx4] =
                make_float4(p0.x + bvv, p0.y + bvv, p1.x + bvv, p1.y + bvv);
            *(float4*)&op[32 + tx4] =
                make_float4(p2.x + bvv, p2.y + bvv, p3.x + bvv, p3.y + bvv);
        }
    }
}

// ---------------- instance norm per (b,c) row over N; optional act + residual
// act: 0 none, 1 exact gelu, 2 relu
__global__ __launch_bounds__(256) void inorm_kernel(
    const float* __restrict__ in, float* __restrict__ out,
    const float* __restrict__ res, int act)
{
    int row = blockIdx.x;
    const float* p = in + (size_t)row * NN;
    int tid = threadIdx.x;
    float s = 0.f, s2 = 0.f;
    for (int i = tid; i < NN; i += 256) { float v = p[i]; s += v; s2 += v * v; }
    __shared__ float r0s[256], r1s[256];
    r0s[tid] = s; r1s[tid] = s2;
    __syncthreads();
    for (int st = 128; st > 0; st >>= 1) {
        if (tid < st) { r0s[tid] += r0s[tid + st]; r1s[tid] += r1s[tid + st]; }
        __syncthreads();
    }
    __shared__ float msh, rsh;
    if (tid == 0) {
        float mean = r0s[0] * (1.f / NN);
        float var  = r1s[0] * (1.f / NN) - mean * mean;
        msh = mean; rsh = rsqrtf(var + EPS_);
    }
    __syncthreads();
    float mean = msh, rstd = rsh;
    const float* rq = res ? res + (size_t)row * NN : nullptr;
    float* op = out + (size_t)row * NN;
    for (int i = tid; i < NN; i += 256) {
        float v = (p[i] - mean) * rstd;
        if (act == 1) v = 0.5f * v * (1.f + erff(v * 0.70710678118654752f));
        else if (act == 2) v = fmaxf(v, 0.f);
        if (rq) v += rq[i];
        op[i] = v;
    }
}

// ---------------- l2 normalize over channel dim per (b,n); also emit sq = ||xn||^2
__global__ __launch_bounds__(256) void l2norm_kernel(
    const float* __restrict__ xf, float* __restrict__ xn, float* __restrict__ sq)
{
    int t = blockIdx.x * 256 + threadIdx.x;
    if (t >= BB * NN) return;
    int b = t / NN, n = t - b * NN;
    const float* p = xf + (size_t)b * CC * NN + n;
    float s = 0.f;
    #pragma unroll 16
    for (int c = 0; c < CC; c++) { float v = p[(size_t)c * NN]; s += v * v; }
    float inv = 1.f / fmaxf(sqrtf(s), 1e-12f);
    float* q = xn + (size_t)b * CC * NN + n;
    #pragma unroll 16
    for (int c = 0; c < CC; c++) q[(size_t)c * NN] = p[(size_t)c * NN] * inv;
    sq[t] = s * inv * inv;
}

// ---------------- fused pairwise distance + top-9 smallest
// 256 threads, 64 n-rows per block; thread = 2 rows x 8 m-cols.
// m-tiles of 128 (two 64-col halves per barrier period) to amortize
// load-barrier latency. Branchless register-resident sorted top-9.
__device__ __forceinline__ void ins9(float v, int m, float tv[KK], int ti[KK])
{
    bool c[KK];
    #pragma unroll
    for (int k = 0; k < KK; k++) c[k] = v < tv[k];
    tv[8] = c[8] ? (c[7] ? tv[7] : v) : tv[8];
    ti[8] = c[8] ? (c[7] ? ti[7] : m) : ti[8];
    #pragma unroll
    for (int k = 7; k >= 1; k--) {
        tv[k] = c[k - 1] ? tv[k - 1] : (c[k] ? v : tv[k]);
        ti[k] = c[k - 1] ? ti[k - 1] : (c[k] ? m : ti[k]);
    }
    tv[0] = c[0] ? v : tv[0];
    ti[0] = c[0] ? m : ti[0];
}

__global__ __launch_bounds__(256, 3) void dist_topk_kernel(
    const float* __restrict__ xn, const float* __restrict__ sq,
    const float* __restrict__ rp, int* __restrict__ oidx)
{
    extern __shared__ float dsm[];
    float* Xn_s = dsm;             // [c][64 n-rows]   24 KB
    float* sh2  = dsm + CC * 64;   // [c][128 m-cols]  48 KB; reused for merge

    int b = blockIdx.y;
    int n0 = blockIdx.x * 64;
    int tid = threadIdx.x;
    int g   = tid >> 3;          // 0..31 row group
    int mc4 = (tid & 7) * 4;     // 0..28 col group (two float4 halves)
    int r0 = g * 2, r1 = r0 + 1;

    const float* xb = xn + (size_t)b * CC * NN;
    for (int t = tid; t < CC * 16; t += 256) {
        int c = t >> 4, q = (t & 15) * 4;
        *(float4*)&Xn_s[c * 64 + q] = *(const float4*)&xb[(size_t)c * NN + n0 + q];
    }
    __syncthreads();

    float2 sqn2 = *(const float2*)&sq[b * NN + n0 + r0];
    float sqn0 = sqn2.x, sqn1 = sqn2.y;

    float tv0[KK], tv1[KK]; int ti0[KK], ti1[KK];
    #pragma unroll
    for (int k = 0; k < KK; k++) { tv0[k] = 1e30f; tv1[k] = 1e30f; ti0[k] = 0; ti1[k] = 0; }

    for (int m0 = 0; m0 < NN; m0 += 128) {
        __syncthreads();
        if (m0 + 128 <= NN) {
            for (int t = tid; t < CC * 32; t += 256) {
                int c = t >> 5, q = (t & 31) * 4;
                *(float4*)&sh2[c * 128 + q] =
                    *(const float4*)&xb[(size_t)c * NN + m0 + q];
            }
        } else {
            for (int t = tid; t < CC * 16; t += 256) {
                int c = t >> 4, q = (t & 15) * 4;
                *(float4*)&sh2[c * 128 + q] =
                    *(const float4*)&xb[(size_t)c * NN + m0 + q];
            }
        }
        __syncthreads();
        #pragma unroll 1
        for (int h = 0; h < 2; h++) {
            int m0h = m0 + h * 64;
            if (m0h >= NN) break;
            const float* sb = sh2 + h * 64;
            ull acc0[4], acc1[4];
            #pragma unroll
            for (int j = 0; j < 4; j++) { acc0[j] = 0ull; acc1[j] = 0ull; }
            #pragma unroll 8
            for (int c = 0; c < CC; c++) {
                float2 a = *(const float2*)&Xn_s[c * 64 + r0];            // broadcast
                ulonglong2 blp = *(const ulonglong2*)&sb[c * 128 + mc4];  // free pairs
                ulonglong2 brp = *(const ulonglong2*)&sb[c * 128 + 32 + mc4];
                ull bp[4] = {blp.x, blp.y, brp.x, brp.y};
                ull a0 = pack2(a.x, a.x), a1 = pack2(a.y, a.y);
                #pragma unroll
                for (int j = 0; j < 4; j++) {
                    ffma2(acc0[j], a0, bp[j]);
                    ffma2(acc1[j], a1, bp[j]);
                }
            }
            // epilogue: dist + branchless topk insert (16B-aligned vector loads)
            const float* sqm = sq + b * NN + m0h;
            float4 sqL = *(const float4*)&sqm[mc4];
            float4 sqR = *(const float4*)&sqm[32 + mc4];
            float sv[8] = {sqL.x, sqL.y, sqL.z, sqL.w, sqR.x, sqR.y, sqR.z, sqR.w};
            const float* rpr0 = rp + (size_t)(n0 + r0) * NN + m0h;
            const float* rpr1 = rp + (size_t)(n0 + r1) * NN + m0h;
            float4 rp0L = *(const float4*)&rpr0[mc4];
            float4 rp0R = *(const float4*)&rpr0[32 + mc4];
            float4 rp1L = *(const float4*)&rpr1[mc4];
            float4 rp1R = *(const float4*)&rpr1[32 + mc4];
            float r0v[8] = {rp0L.x, rp0L.y, rp0L.z, rp0L.w,
                            rp0R.x, rp0R.y, rp0R.z, rp0R.w};
            float r1v[8] = {rp1L.x, rp1L.y, rp1L.z, rp1L.w,
                            rp1R.x, rp1R.y, rp1R.z, rp1R.w};
            float2 p00 = unpack2(acc0[0]), p01 = unpack2(acc0[1]);
            float2 p02 = unpack2(acc0[2]), p03 = unpack2(acc0[3]);
            float2 p10 = unpack2(acc1[0]), p11 = unpack2(acc1[1]);
            float2 p12 = unpack2(acc1[2]), p13 = unpack2(acc1[3]);
            float dot0[8] = {p00.x, p00.y, p01.x, p01.y, p02.x, p02.y, p03.x, p03.y};
            float dot1[8] = {p10.x, p10.y, p11.x, p11.y, p12.x, p12.y, p13.x, p13.y};
            #pragma unroll
            for (int j = 0; j < 8; j++) {
                int m = m0h + (j < 4 ? mc4 + j : 32 + mc4 + (j - 4));
                float d0 = fmaf(-2.f, dot0[j], sqn0 + sv[j] + r0v[j]);
                float d1 = fmaf(-2.f, dot1[j], sqn1 + sv[j] + r1v[j]);
                ins9(d0, m, tv0, ti0);
                ins9(d1, m, tv1, ti1);
            }
        }
    }

    // ---------- merge: 8 sorted partial lists per row, single pass ----------
    __syncthreads();
    float* cv = dsm;                        // [64][8][9] values (4608 f)
    int*   ci = (int*)(dsm + 64 * 8 * KK);  // [64][8][9] indices
    int cg = tid & 7;
    #pragma unroll
    for (int k = 0; k < KK; k++) {
        cv[(r0 * 8 + cg) * KK + k] = tv0[k]; ci[(r0 * 8 + cg) * KK + k] = ti0[k];
        cv[(r1 * 8 + cg) * KK + k] = tv1[k]; ci[(r1 * 8 + cg) * KK + k] = ti1[k];
    }
    __syncthreads();
    if (tid < 64) {
        float* rv = cv + tid * 8 * KK;
        int*   ri = ci + tid * 8 * KK;
        int* op = oidx + ((size_t)b * NN + n0 + tid) * KK;
        for (int k = 0; k < KK; k++) {
            float best = 2e30f; int bi = 0, bt = 0;
            for (int t = 0; t < 8 * KK; t++) {
                float v = rv[t];
                if (v < best) { best = v; bi = ri[t]; bt = t; }
            }
            rv[bt] = 3e30f;   // consume
            op[k] = bi;
        }
    }
}

// ---------------- gather neighbors, max(x_j - x_i), write channel-interleaved (B,2C,N)
__global__ __launch_bounds__(256) void aggregate_kernel(
    const float* __restrict__ xf, const int* __restrict__ idx, float* __restrict__ y)
{
    int bc = blockIdx.x;            // b*CC + c
    __shared__ float row[NN];
    const float* p = xf + (size_t)bc * NN;
    for (int i = threadIdx.x; i < NN; i += 256) row[i] = p[i];
    __syncthreads();
    int b = bc / CC, c = bc - b * CC;
    const int* ip = idx + (size_t)b * NN * KK;
    float* y0 = y + ((size_t)b * C2 + 2 * c) * NN;
    float* y1 = y0 + NN;
    for (int n = threadIdx.x; n < NN; n += 256) {
        float xi = row[n];
        float mx = -3e38f;
        #pragma unroll
        for (int k = 0; k < KK; k++) {
            int j = ip[n * KK + k];
            mx = fmaxf(mx, row[j] - xi);
        }
        y0[n] = xi;
        y1[n] = mx;
    }
}

// ---------------- host orchestration ----------------
static constexpr int DIST_SMEM = CC * 192 * (int)sizeof(float);   // 73728 B

static void run_conv(const float* X, const float* W, const float* bias,
                     float* out, int Cout, int Cin)
{
    dim3 g(NN / 64, (Cout + 63) / 64, BB);
    gemm_bias_kernel<<<g, 128>>>(X, W, bias, out, Cout, Cin);
}
static void run_inorm(const float* in, float* out, const float* res, int Crows, int act)
{
    inorm_kernel<<<BB * Crows, 256>>>(in, out, res, act);
}

extern "C" void kernel_launch(void* const* d_in, const int* in_sizes, int n_in,
                              void* d_out, int out_size)
{
    (void)in_sizes; (void)n_in; (void)out_size;
    const float* x  = (const float*)d_in[0];
    const float* rp = (const float*)d_in[1];
    const float* P[20];
    for (int i = 0; i < 20; i++) P[i] = (const float*)d_in[2 + i];

    cudaFuncSetAttribute(dist_topk_kernel,
                         cudaFuncAttributeMaxDynamicSharedMemorySize, DIST_SMEM);

    float *act, *t1, *xf, *xnp, *sqp, *big; int* idxp;
    cudaGetSymbolAddress((void**)&act,  g_act);
    cudaGetSymbolAddress((void**)&t1,   g_t1);
    cudaGetSymbolAddress((void**)&xf,   g_xf);
    cudaGetSymbolAddress((void**)&xnp,  g_xn);
    cudaGetSymbolAddress((void**)&sqp,  g_sq);
    cudaGetSymbolAddress((void**)&idxp, g_idx);
    cudaGetSymbolAddress((void**)&big,  g_big);
    float* y2 = big;                          // (B,2C,N)
    float* t3 = big + (size_t)BB * C2 * NN;   // (B,2C,N)
    float* out = (float*)d_out;

    auto grapher = [&](const float* inx,
                       const float* w1, const float* b1,
                       const float* mw, const float* mb,
                       const float* w2, const float* b2, float* outp) {
        run_conv(inx, w1, b1, t1, CC, CC);
        run_inorm(t1, xf, nullptr, CC, 0);                          // xf
        l2norm_kernel<<<(BB * NN + 255) / 256, 256>>>(xf, xnp, sqp);
        dim3 dg(NN / 64, BB);
        dist_topk_kernel<<<dg, 256, DIST_SMEM>>>(xnp, sqp, rp, idxp);
        aggregate_kernel<<<BB * CC, 256>>>(xf, idxp, y2);           // (B,2C,N)
        run_conv(y2, mw, mb, t3, C2, C2);
        run_inorm(t3, t3, nullptr, C2, 1);                          // gelu, in-place
        run_conv(t3, w2, b2, t1, CC, C2);
        run_inorm(t1, outp, inx, CC, 0);                            // + shortcut
    };
    auto ffn = [&](float* a, const float* w1, const float* b1,
                   const float* w2, const float* b2) {
        run_conv(a, w1, b1, big, C4, CC);
        run_inorm(big, big, nullptr, C4, 1);                        // gelu, in-place
        run_conv(big, w2, b2, t1, CC, C4);
        run_inorm(t1, a, a, CC, 0);                                 // + shortcut
    };

    grapher(x, P[0], P[1], P[2], P[3], P[4], P[5], act);
    ffn(act, P[12], P[13], P[14], P[15]);
    run_inorm(act, act, nullptr, CC, 2);                            // relu(inorm)
    grapher(act, P[6], P[7], P[8], P[9], P[10], P[11], act);
    ffn(act, P[16], P[17], P[18], P[19]);
    run_inorm(act, out, x, CC, 0);                                  // x + inorm(y)
}

// round 16
// speedup vs baseline: 1.1944x; 1.0473x over previous
#include <cuda_runtime.h>
#include <math.h>

static constexpr int BB = 8;
static constexpr int CC = 96;
static constexpr int C2 = 192;
static constexpr int C4 = 384;
static constexpr int NN = 3136;   // 56*56
static constexpr int KK = 9;
static constexpr float EPS_ = 1e-5f;

// ---------------- scratch (no allocations allowed) ----------------
__device__ float g_act[BB * CC * NN];
__device__ float g_t1 [BB * CC * NN];
__device__ float g_xf [BB * CC * NN];
__device__ float g_xn [BB * CC * NN];
__device__ float g_sq [BB * NN];
__device__ int   g_idx[BB * NN * KK];
__device__ float g_big[BB * C4 * NN];   // ffn hidden; also 2C y2 + 2C t3 for grapher

// ---------------- packed f32x2 helpers (FFMA2 via PTX) ----------------
typedef unsigned long long ull;
__device__ __forceinline__ ull pack2(float lo, float hi) {
    ull r;
    asm("mov.b64 %0, {%1, %2};" : "=l"(r) : "f"(lo), "f"(hi));
    return r;
}
__device__ __forceinline__ void ffma2(ull& d, ull a, ull b) {
    asm("fma.rn.f32x2 %0, %1, %2, %3;" : "=l"(d) : "l"(a), "l"(b), "l"(d));
}
__device__ __forceinline__ float2 unpack2(ull v) {
    float2 f;
    asm("mov.b64 {%0, %1}, %2;" : "=f"(f.x), "=f"(f.y) : "l"(v));
    return f;
}

// ---------------- 1x1 conv == batched GEMM: out[b,o,n] = sum_c W[o,c] X[b,c,n] + bias[o]
// 128 threads, 96(o) x 64(n) tile, k-chunk 96; thread = 6 o-rows x 8 n-cols.
// Cout and Cin are always multiples of 96 -> no bounds checks, no o-tile waste.
static constexpr int WS_STRIDE = 98;   // padded: conflict-free transpose store, 8B-aligned a-loads
static constexpr int CONV_SMEM = (96 * WS_STRIDE + 96 * 64) * (int)sizeof(float);  // 62 KB

__global__ __launch_bounds__(128) void gemm_bias_kernel(
    const float* __restrict__ X, const float* __restrict__ W,
    const float* __restrict__ bias, float* __restrict__ out,
    int Cout, int Cin)
{
    extern __shared__ float csm[];
    float* Ws = csm;                    // [k][o] stride 98
    float* Xs = csm + 96 * WS_STRIDE;   // [k][64]

    int b  = blockIdx.z;
    int n0 = blockIdx.x * 64;
    int o0 = blockIdx.y * 96;
    int tid = threadIdx.x;
    int og  = tid >> 3;          // 0..15
    int nc4 = (tid & 7) * 4;     // 0..28
    int obase = og * 6;          // 0..90 (even -> 8B-aligned float2 loads)

    ull acc[6][4];
    #pragma unroll
    for (int i = 0; i < 6; i++)
        #pragma unroll
        for (int j = 0; j < 4; j++) acc[i][j] = 0ull;
    const float* Xb = X + (size_t)b * Cin * NN;

    for (int kt = 0; kt < Cin; kt += 96) {
        // load W chunk: 96 o-rows x 96 k, transposed to [k][o]
        for (int t = tid; t < 96 * 24; t += 128) {
            int o = t / 24, kq = t - o * 24;
            float4 w = *(const float4*)&W[(size_t)(o0 + o) * Cin + kt + kq * 4];
            Ws[(kq * 4 + 0) * WS_STRIDE + o] = w.x;
            Ws[(kq * 4 + 1) * WS_STRIDE + o] = w.y;
            Ws[(kq * 4 + 2) * WS_STRIDE + o] = w.z;
            Ws[(kq * 4 + 3) * WS_STRIDE + o] = w.w;
        }
        // load X chunk: 96 k-rows x 64 n
        for (int t = tid; t < 96 * 16; t += 128) {
            int k = t >> 4, nq = t & 15;
            *(float4*)&Xs[k * 64 + nq * 4] =
                *(const float4*)&Xb[(size_t)(kt + k) * NN + n0 + nq * 4];
        }
        __syncthreads();
        #pragma unroll 8
        for (int k = 0; k < 96; k++) {
            const float* wr = &Ws[k * WS_STRIDE + obase];
            float2 a01 = *(const float2*)&wr[0];
            float2 a23 = *(const float2*)&wr[2];
            float2 a45 = *(const float2*)&wr[4];
            ulonglong2 bl = *(const ulonglong2*)&Xs[k * 64 + nc4];
            ulonglong2 br = *(const ulonglong2*)&Xs[k * 64 + 32 + nc4];
            ull bp[4] = {bl.x, bl.y, br.x, br.y};
            ull ap[6] = {pack2(a01.x, a01.x), pack2(a01.y, a01.y),
                         pack2(a23.x, a23.x), pack2(a23.y, a23.y),
                         pack2(a45.x, a45.x), pack2(a45.y, a45.y)};
            #pragma unroll
            for (int i = 0; i < 6; i++)
                #pragma unroll
                for (int j = 0; j < 4; j++)
                    ffma2(acc[i][j], ap[i], bp[j]);
        }
        __syncthreads();
    }
    #pragma unroll
    for (int i = 0; i < 6; i++) {
        int o = o0 + obase + i;
        float bvv = bias[o];
        float* op = out + ((size_t)b * Cout + o) * NN + n0;
        float2 p0 = unpack2(acc[i][0]), p1 = unpack2(acc[i][1]);
        float2 p2 = unpack2(acc[i][2]), p3 = unpack2(acc[i][3]);
        *(float4*)&op[nc4] =
            make_float4(p0.x + bvv, p0.y + bvv, p1.x + bvv, p1.y + bvv);
        *(float4*)&op[32 + nc4] =
            make_float4(p2.x + bvv, p2.y + bvv, p3.x + bvv, p3.y + bvv);
    }
}

// ---------------- instance norm per (b,c) row over N; optional act + residual
// act: 0 none, 1 exact gelu, 2 relu
__global__ __launch_bounds__(256) void inorm_kernel(
    const float* __restrict__ in, float* __restrict__ out,
    const float* __restrict__ res, int act)
{
    int row = blockIdx.x;
    const float* p = in + (size_t)row * NN;
    int tid = threadIdx.x;
    float s = 0.f, s2 = 0.f;
    for (int i = tid; i < NN; i += 256) { float v = p[i]; s += v; s2 += v * v; }
    __shared__ float r0s[256], r1s[256];
    r0s[tid] = s; r1s[tid] = s2;
    __syncthreads();
    for (int st = 128; st > 0; st >>= 1) {
        if (tid < st) { r0s[tid] += r0s[tid + st]; r1s[tid] += r1s[tid + st]; }
        __syncthreads();
    }
    __shared__ float msh, rsh;
    if (tid == 0) {
        float mean = r0s[0] * (1.f / NN);
        float var  = r1s[0] * (1.f / NN) - mean * mean;
        msh = mean; rsh = rsqrtf(var + EPS_);
    }
    __syncthreads();
    float mean = msh, rstd = rsh;
    const float* rq = res ? res + (size_t)row * NN : nullptr;
    float* op = out + (size_t)row * NN;
    for (int i = tid; i < NN; i += 256) {
        float v = (p[i] - mean) * rstd;
        if (act == 1) v = 0.5f * v * (1.f + erff(v * 0.70710678118654752f));
        else if (act == 2) v = fmaxf(v, 0.f);
        if (rq) v += rq[i];
        op[i] = v;
    }
}

// ---------------- l2 normalize over channel dim per (b,n); also emit sq = ||xn||^2
__global__ __launch_bounds__(256) void l2norm_kernel(
    const float* __restrict__ xf, float* __restrict__ xn, float* __restrict__ sq)
{
    int t = blockIdx.x * 256 + threadIdx.x;
    if (t >= BB * NN) return;
    int b = t / NN, n = t - b * NN;
    const float* p = xf + (size_t)b * CC * NN + n;
    float s = 0.f;
    #pragma unroll 16
    for (int c = 0; c < CC; c++) { float v = p[(size_t)c * NN]; s += v * v; }
    float inv = 1.f / fmaxf(sqrtf(s), 1e-12f);
    float* q = xn + (size_t)b * CC * NN + n;
    #pragma unroll 16
    for (int c = 0; c < CC; c++) q[(size_t)c * NN] = p[(size_t)c * NN] * inv;
    sq[t] = s * inv * inv;
}

// ---------------- fused pairwise distance + top-9 smallest
// 256 threads, 64 n-rows per block; thread = 2 rows x 8 m-cols.
// m-tiles of 128 (two 64-col halves per barrier period) to amortize
// load-barrier latency. Branchless register-resident sorted top-9.
__device__ __forceinline__ void ins9(float v, int m, float tv[KK], int ti[KK])
{
    bool c[KK];
    #pragma unroll
    for (int k = 0; k < KK; k++) c[k] = v < tv[k];
    tv[8] = c[8] ? (c[7] ? tv[7] : v) : tv[8];
    ti[8] = c[8] ? (c[7] ? ti[7] : m) : ti[8];
    #pragma unroll
    for (int k = 7; k >= 1; k--) {
        tv[k] = c[k - 1] ? tv[k - 1] : (c[k] ? v : tv[k]);
        ti[k] = c[k - 1] ? ti[k - 1] : (c[k] ? m : ti[k]);
    }
    tv[0] = c[0] ? v : tv[0];
    ti[0] = c[0] ? m : ti[0];
}

__global__ __launch_bounds__(256, 3) void dist_topk_kernel(
    const float* __restrict__ xn, const float* __restrict__ sq,
    const float* __restrict__ rp, int* __restrict__ oidx)
{
    extern __shared__ float dsm[];
    float* Xn_s = dsm;             // [c][64 n-rows]   24 KB
    float* sh2  = dsm + CC * 64;   // [c][128 m-cols]  48 KB; reused for merge

    int b = blockIdx.y;
    int n0 = blockIdx.x * 64;
    int tid = threadIdx.x;
    int g   = tid >> 3;          // 0..31 row group
    int mc4 = (tid & 7) * 4;     // 0..28 col group (two float4 halves)
    int r0 = g * 2, r1 = r0 + 1;

    const float* xb = xn + (size_t)b * CC * NN;
    for (int t = tid; t < CC * 16; t += 256) {
        int c = t >> 4, q = (t & 15) * 4;
        *(float4*)&Xn_s[c * 64 + q] = *(const float4*)&xb[(size_t)c * NN + n0 + q];
    }
    __syncthreads();

    float2 sqn2 = *(const float2*)&sq[b * NN + n0 + r0];
    float sqn0 = sqn2.x, sqn1 = sqn2.y;

    float tv0[KK], tv1[KK]; int ti0[KK], ti1[KK];
    #pragma unroll
    for (int k = 0; k < KK; k++) { tv0[k] = 1e30f; tv1[k] = 1e30f; ti0[k] = 0; ti1[k] = 0; }

    for (int m0 = 0; m0 < NN; m0 += 128) {
        __syncthreads();
        if (m0 + 128 <= NN) {
            for (int t = tid; t < CC * 32; t += 256) {
                int c = t >> 5, q = (t & 31) * 4;
                *(float4*)&sh2[c * 128 + q] =
                    *(const float4*)&xb[(size_t)c * NN + m0 + q];
            }
        } else {
            for (int t = tid; t < CC * 16; t += 256) {
                int c = t >> 4, q = (t & 15) * 4;
                *(float4*)&sh2[c * 128 + q] =
                    *(const float4*)&xb[(size_t)c * NN + m0 + q];
            }
        }
        __syncthreads();
        #pragma unroll 1
        for (int h = 0; h < 2; h++) {
            int m0h = m0 + h * 64;
            if (m0h >= NN) break;
            const float* sb = sh2 + h * 64;
            ull acc0[4], acc1[4];
            #pragma unroll
            for (int j = 0; j < 4; j++) { acc0[j] = 0ull; acc1[j] = 0ull; }
            #pragma unroll 8
            for (int c = 0; c < CC; c++) {
                float2 a = *(const float2*)&Xn_s[c * 64 + r0];            // broadcast
                ulonglong2 blp = *(const ulonglong2*)&sb[c * 128 + mc4];  // free pairs
                ulonglong2 brp = *(const ulonglong2*)&sb[c * 128 + 32 + mc4];
                ull bp[4] = {blp.x, blp.y, brp.x, brp.y};
                ull a0 = pack2(a.x, a.x), a1 = pack2(a.y, a.y);
                #pragma unroll
                for (int j = 0; j < 4; j++) {
                    ffma2(acc0[j], a0, bp[j]);
                    ffma2(acc1[j], a1, bp[j]);
                }
            }
            // epilogue: dist + branchless topk insert (16B-aligned vector loads)
            const float* sqm = sq + b * NN + m0h;
            float4 sqL = *(const float4*)&sqm[mc4];
            float4 sqR = *(const float4*)&sqm[32 + mc4];
            float sv[8] = {sqL.x, sqL.y, sqL.z, sqL.w, sqR.x, sqR.y, sqR.z, sqR.w};
            const float* rpr0 = rp + (size_t)(n0 + r0) * NN + m0h;
            const float* rpr1 = rp + (size_t)(n0 + r1) * NN + m0h;
            float4 rp0L = *(const float4*)&rpr0[mc4];
            float4 rp0R = *(const float4*)&rpr0[32 + mc4];
            float4 rp1L = *(const float4*)&rpr1[mc4];
            float4 rp1R = *(const float4*)&rpr1[32 + mc4];
            float r0v[8] = {rp0L.x, rp0L.y, rp0L.z, rp0L.w,
                            rp0R.x, rp0R.y, rp0R.z, rp0R.w};
            float r1v[8] = {rp1L.x, rp1L.y, rp1L.z, rp1L.w,
                            rp1R.x, rp1R.y, rp1R.z, rp1R.w};
            float2 p00 = unpack2(acc0[0]), p01 = unpack2(acc0[1]);
            float2 p02 = unpack2(acc0[2]), p03 = unpack2(acc0[3]);
            float2 p10 = unpack2(acc1[0]), p11 = unpack2(acc1[1]);
            float2 p12 = unpack2(acc1[2]), p13 = unpack2(acc1[3]);
            float dot0[8] = {p00.x, p00.y, p01.x, p01.y, p02.x, p02.y, p03.x, p03.y};
            float dot1[8] = {p10.x, p10.y, p11.x, p11.y, p12.x, p12.y, p13.x, p13.y};
            #pragma unroll
            for (int j = 0; j < 8; j++) {
                int m = m0h + (j < 4 ? mc4 + j : 32 + mc4 + (j - 4));
                float d0 = fmaf(-2.f, dot0[j], sqn0 + sv[j] + r0v[j]);
                float d1 = fmaf(-2.f, dot1[j], sqn1 + sv[j] + r1v[j]);
                ins9(d0, m, tv0, ti0);
                ins9(d1, m, tv1, ti1);
            }
        }
    }

    // ---------- merge: 8 sorted partial lists per row, single pass ----------
    __syncthreads();
    float* cv = dsm;                        // [64][8][9] values (4608 f)
    int*   ci = (int*)(dsm + 64 * 8 * KK);  // [64][8][9] indices
    int cg = tid & 7;
    #pragma unroll
    for (int k = 0; k < KK; k++) {
        cv[(r0 * 8 + cg) * KK + k] = tv0[k]; ci[(r0 * 8 + cg) * KK + k] = ti0[k];
        cv[(r1 * 8 + cg) * KK + k] = tv1[k]; ci[(r1 * 8 + cg) * KK + k] = ti1[k];
    }
    __syncthreads();
    if (tid < 64) {
        float* rv = cv + tid * 8 * KK;
        int*   ri = ci + tid * 8 * KK;
        int* op = oidx + ((size_t)b * NN + n0 + tid) * KK;
        for (int k = 0; k < KK; k++) {
            float best = 2e30f; int bi = 0, bt = 0;
            for (int t = 0; t < 8 * KK; t++) {
                float v = rv[t];
                if (v < best) { best = v; bi = ri[t]; bt = t; }
            }
            rv[bt] = 3e30f;   // consume
            op[k] = bi;
        }
    }
}

// ---------------- gather neighbors, max(x_j - x_i), write channel-interleaved (B,2C,N)
__global__ __launch_bounds__(256) void aggregate_kernel(
    const float* __restrict__ xf, const int* __restrict__ idx, float* __restrict__ y)
{
    int bc = blockIdx.x;            // b*CC + c
    __shared__ float row[NN];
    const float* p = xf + (size_t)bc * NN;
    for (int i = threadIdx.x; i < NN; i += 256) row[i] = p[i];
    __syncthreads();
    int b = bc / CC, c = bc - b * CC;
    const int* ip = idx + (size_t)b * NN * KK;
    float* y0 = y + ((size_t)b * C2 + 2 * c) * NN;
    float* y1 = y0 + NN;
    for (int n = threadIdx.x; n < NN; n += 256) {
        float xi = row[n];
        float mx = -3e38f;
        #pragma unroll
        for (int k = 0; k < KK; k++) {
            int j = ip[n * KK + k];
            mx = fmaxf(mx, row[j] - xi);
        }
        y0[n] = xi;
        y1[n] = mx;
    }
}

// ---------------- host orchestration ----------------
static constexpr int DIST_SMEM = CC * 192 * (int)sizeof(float);   // 73728 B

static void run_conv(const float* X, const float* W, const float* bias,
                     float* out, int Cout, int Cin)
{
    dim3 g(NN / 64, Cout / 96, BB);
    gemm_bias_kernel<<<g, 128, CONV_SMEM>>>(X, W, bias, out, Cout, Cin);
}
static void run_inorm(const float* in, float* out, const float* res, int Crows, int act)
{
    inorm_kernel<<<BB * Crows, 256>>>(in, out, res, act);
}

extern "C" void kernel_launch(void* const* d_in, const int* in_sizes, int n_in,
                              void* d_out, int out_size)
{
    (void)in_sizes; (void)n_in; (void)out_size;
    const float* x  = (const float*)d_in[0];
    const float* rp = (const float*)d_in[1];
    const float* P[20];
    for (int i = 0; i < 20; i++) P[i] = (const float*)d_in[2 + i];

    cudaFuncSetAttribute(dist_topk_kernel,
                         cudaFuncAttributeMaxDynamicSharedMemorySize, DIST_SMEM);
    cudaFuncSetAttribute(gemm_bias_kernel,
                         cudaFuncAttributeMaxDynamicSharedMemorySize, CONV_SMEM);

    float *act, *t1, *xf, *xnp, *sqp, *big; int* idxp;
    cudaGetSymbolAddress((void**)&act,  g_act);
    cudaGetSymbolAddress((void**)&t1,   g_t1);
    cudaGetSymbolAddress((void**)&xf,   g_xf);
    cudaGetSymbolAddress((void**)&xnp,  g_xn);
    cudaGetSymbolAddress((void**)&sqp,  g_sq);
    cudaGetSymbolAddress((void**)&idxp, g_idx);
    cudaGetSymbolAddress((void**)&big,  g_big);
    float* y2 = big;                          // (B,2C,N)
    float* t3 = big + (size_t)BB * C2 * NN;   // (B,2C,N)
    float* out = (float*)d_out;

    auto grapher = [&](const float* inx,
                       const float* w1, const float* b1,
                       const float* mw, const float* mb,
                       const float* w2, const float* b2, float* outp) {
        run_conv(inx, w1, b1, t1, CC, CC);
        run_inorm(t1, xf, nullptr, CC, 0);                          // xf
        l2norm_kernel<<<(BB * NN + 255) / 256, 256>>>(xf, xnp, sqp);
        dim3 dg(NN / 64, BB);
        dist_topk_kernel<<<dg, 256, DIST_SMEM>>>(xnp, sqp, rp, idxp);
        aggregate_kernel<<<BB * CC, 256>>>(xf, idxp, y2);           // (B,2C,N)
        run_conv(y2, mw, mb, t3, C2, C2);
        run_inorm(t3, t3, nullptr, C2, 1);                          // gelu, in-place
        run_conv(t3, w2, b2, t1, CC, C2);
        run_inorm(t1, outp, inx, CC, 0);                            // + shortcut
    };
    auto ffn = [&](float* a, const float* w1, const float* b1,
                   const float* w2, const float* b2) {
        run_conv(a, w1, b1, big, C4, CC);
        run_inorm(big, big, nullptr, C4, 1);                        // gelu, in-place
        run_conv(big, w2, b2, t1, CC, C4);
        run_inorm(t1, a, a, CC, 0);                                 // + shortcut
    };

    grapher(x, P[0], P[1], P[2], P[3], P[4], P[5], act);
    ffn(act, P[12], P[13], P[14], P[15]);
    run_inorm(act, act, nullptr, CC, 2);                            // relu(inorm)
    grapher(act, P[6], P[7], P[8], P[9], P[10], P[11], act);
    ffn(act, P[16], P[17], P[18], P[19]);
    run_inorm(act, out, x, CC, 0);                                  // x + inorm(y)
}

// round 17
// speedup vs baseline: 1.2142x; 1.0166x over previous
#include <cuda_runtime.h>
#include <math.h>

static constexpr int BB = 8;
static constexpr int CC = 96;
static constexpr int C2 = 192;
static constexpr int C4 = 384;
static constexpr int NN = 3136;   // 56*56
static constexpr int KK = 9;
static constexpr float EPS_ = 1e-5f;

// ---------------- scratch (no allocations allowed) ----------------
__device__ float g_act[BB * CC * NN];
__device__ float g_t1 [BB * CC * NN];
__device__ float g_xf [BB * CC * NN];
__device__ float g_xn [BB * CC * NN];
__device__ float g_sq [BB * NN];
__device__ int   g_idx[BB * NN * KK];
__device__ float g_big[BB * C4 * NN];   // ffn hidden; also 2C y2 + 2C t3 for grapher

// ---------------- packed f32x2 helpers (FFMA2 via PTX) ----------------
typedef unsigned long long ull;
__device__ __forceinline__ ull pack2(float lo, float hi) {
    ull r;
    asm("mov.b64 %0, {%1, %2};" : "=l"(r) : "f"(lo), "f"(hi));
    return r;
}
__device__ __forceinline__ void ffma2(ull& d, ull a, ull b) {
    asm("fma.rn.f32x2 %0, %1, %2, %3;" : "=l"(d) : "l"(a), "l"(b), "l"(d));
}
__device__ __forceinline__ float2 unpack2(ull v) {
    float2 f;
    asm("mov.b64 {%0, %1}, %2;" : "=f"(f.x), "=f"(f.y) : "l"(v));
    return f;
}

// ---------------- 1x1 conv == batched GEMM: out[b,o,n] = sum_c W[o,c] X[b,c,n] + bias[o]
// 128 threads, 96(o) x 64(n) tile, k-chunk 96; thread = 6 o-rows x 8 n-cols.
// Cout and Cin are always multiples of 96 -> no bounds checks, no o-tile waste.
static constexpr int WS_STRIDE = 98;   // padded: conflict-free transpose store, 8B-aligned a-loads
static constexpr int CONV_SMEM = (96 * WS_STRIDE + 96 * 64) * (int)sizeof(float);  // 62 KB

__global__ __launch_bounds__(128) void gemm_bias_kernel(
    const float* __restrict__ X, const float* __restrict__ W,
    const float* __restrict__ bias, float* __restrict__ out,
    int Cout, int Cin)
{
    extern __shared__ float csm[];
    float* Ws = csm;                    // [k][o] stride 98
    float* Xs = csm + 96 * WS_STRIDE;   // [k][64]

    int b  = blockIdx.z;
    int n0 = blockIdx.x * 64;
    int o0 = blockIdx.y * 96;
    int tid = threadIdx.x;
    int og  = tid >> 3;          // 0..15
    int nc4 = (tid & 7) * 4;     // 0..28
    int obase = og * 6;          // 0..90 (even -> 8B-aligned float2 loads)

    ull acc[6][4];
    #pragma unroll
    for (int i = 0; i < 6; i++)
        #pragma unroll
        for (int j = 0; j < 4; j++) acc[i][j] = 0ull;
    const float* Xb = X + (size_t)b * Cin * NN;

    for (int kt = 0; kt < Cin; kt += 96) {
        // load W chunk: 96 o-rows x 96 k, transposed to [k][o]
        for (int t = tid; t < 96 * 24; t += 128) {
            int o = t / 24, kq = t - o * 24;
            float4 w = *(const float4*)&W[(size_t)(o0 + o) * Cin + kt + kq * 4];
            Ws[(kq * 4 + 0) * WS_STRIDE + o] = w.x;
            Ws[(kq * 4 + 1) * WS_STRIDE + o] = w.y;
            Ws[(kq * 4 + 2) * WS_STRIDE + o] = w.z;
            Ws[(kq * 4 + 3) * WS_STRIDE + o] = w.w;
        }
        // load X chunk: 96 k-rows x 64 n
        for (int t = tid; t < 96 * 16; t += 128) {
            int k = t >> 4, nq = t & 15;
            *(float4*)&Xs[k * 64 + nq * 4] =
                *(const float4*)&Xb[(size_t)(kt + k) * NN + n0 + nq * 4];
        }
        __syncthreads();
        #pragma unroll 8
        for (int k = 0; k < 96; k++) {
            const float* wr = &Ws[k * WS_STRIDE + obase];
            float2 a01 = *(const float2*)&wr[0];
            float2 a23 = *(const float2*)&wr[2];
            float2 a45 = *(const float2*)&wr[4];
            ulonglong2 bl = *(const ulonglong2*)&Xs[k * 64 + nc4];
            ulonglong2 br = *(const ulonglong2*)&Xs[k * 64 + 32 + nc4];
            ull bp[4] = {bl.x, bl.y, br.x, br.y};
            ull ap[6] = {pack2(a01.x, a01.x), pack2(a01.y, a01.y),
                         pack2(a23.x, a23.x), pack2(a23.y, a23.y),
                         pack2(a45.x, a45.x), pack2(a45.y, a45.y)};
            #pragma unroll
            for (int i = 0; i < 6; i++)
                #pragma unroll
                for (int j = 0; j < 4; j++)
                    ffma2(acc[i][j], ap[i], bp[j]);
        }
        __syncthreads();
    }
    #pragma unroll
    for (int i = 0; i < 6; i++) {
        int o = o0 + obase + i;
        float bvv = bias[o];
        float* op = out + ((size_t)b * Cout + o) * NN + n0;
        float2 p0 = unpack2(acc[i][0]), p1 = unpack2(acc[i][1]);
        float2 p2 = unpack2(acc[i][2]), p3 = unpack2(acc[i][3]);
        *(float4*)&op[nc4] =
            make_float4(p0.x + bvv, p0.y + bvv, p1.x + bvv, p1.y + bvv);
        *(float4*)&op[32 + nc4] =
            make_float4(p2.x + bvv, p2.y + bvv, p3.x + bvv, p3.y + bvv);
    }
}

// ---------------- instance norm per (b,c) row over N; optional act + residual
// act: 0 none, 1 exact gelu, 2 relu
// Row cached in smem during the stats pass; normalize pass reads LDS.
__global__ __launch_bounds__(256) void inorm_kernel(
    const float* __restrict__ in, float* __restrict__ out,
    const float* __restrict__ res, int act)
{
    __shared__ float rowc[NN];
    __shared__ float r0s[256], r1s[256];
    int row = blockIdx.x;
    const float* p = in + (size_t)row * NN;
    int tid = threadIdx.x;
    float s = 0.f, s2 = 0.f;
    for (int i = tid; i < NN; i += 256) {
        float v = p[i];
        rowc[i] = v;
        s += v; s2 += v * v;
    }
    r0s[tid] = s; r1s[tid] = s2;
    __syncthreads();
    for (int st = 128; st > 0; st >>= 1) {
        if (tid < st) { r0s[tid] += r0s[tid + st]; r1s[tid] += r1s[tid + st]; }
        __syncthreads();
    }
    __shared__ float msh, rsh;
    if (tid == 0) {
        float mean = r0s[0] * (1.f / NN);
        float var  = r1s[0] * (1.f / NN) - mean * mean;
        msh = mean; rsh = rsqrtf(var + EPS_);
    }
    __syncthreads();
    float mean = msh, rstd = rsh;
    const float* rq = res ? res + (size_t)row * NN : nullptr;
    float* op = out + (size_t)row * NN;
    for (int i = tid; i < NN; i += 256) {
        float v = (rowc[i] - mean) * rstd;
        if (act == 1) v = 0.5f * v * (1.f + erff(v * 0.70710678118654752f));
        else if (act == 2) v = fmaxf(v, 0.f);
        if (rq) v += rq[i];
        op[i] = v;
    }
}

// ---------------- l2 normalize over channel dim per (b,n); also emit sq = ||xn||^2
__global__ __launch_bounds__(256) void l2norm_kernel(
    const float* __restrict__ xf, float* __restrict__ xn, float* __restrict__ sq)
{
    int t = blockIdx.x * 256 + threadIdx.x;
    if (t >= BB * NN) return;
    int b = t / NN, n = t - b * NN;
    const float* p = xf + (size_t)b * CC * NN + n;
    float s = 0.f;
    #pragma unroll 16
    for (int c = 0; c < CC; c++) { float v = p[(size_t)c * NN]; s += v * v; }
    float inv = 1.f / fmaxf(sqrtf(s), 1e-12f);
    float* q = xn + (size_t)b * CC * NN + n;
    #pragma unroll 16
    for (int c = 0; c < CC; c++) q[(size_t)c * NN] = p[(size_t)c * NN] * inv;
    sq[t] = s * inv * inv;
}

// ---------------- fused pairwise distance + top-9 smallest
// 256 threads, 64 n-rows per block; thread = 2 rows x 8 m-cols.
// m-tiles of 128 (two 64-col halves per barrier period).
// ins9: sorted-insert via min/max identity -> critical path = 2 FMNMX (8 cyc);
// index SELs read only OLD state (off the value chain). Bit-exact vs SEL form.
__device__ __forceinline__ void ins9(float v, int m, float tv[KK], int ti[KK])
{
    bool c[KK];
    #pragma unroll
    for (int k = 0; k < KK; k++) c[k] = v < tv[k];
    float nt[KK];
    nt[0] = fminf(tv[0], v);
    #pragma unroll
    for (int k = 1; k < KK; k++) nt[k] = fminf(tv[k], fmaxf(v, tv[k - 1]));
    #pragma unroll
    for (int k = KK - 1; k >= 1; k--)
        ti[k] = c[k] ? (c[k - 1] ? ti[k - 1] : m) : ti[k];
    ti[0] = c[0] ? m : ti[0];
    #pragma unroll
    for (int k = 0; k < KK; k++) tv[k] = nt[k];
}

__global__ __launch_bounds__(256, 3) void dist_topk_kernel(
    const float* __restrict__ xn, const float* __restrict__ sq,
    const float* __restrict__ rp, int* __restrict__ oidx)
{
    extern __shared__ float dsm[];
    float* Xn_s = dsm;             // [c][64 n-rows]   24 KB
    float* sh2  = dsm + CC * 64;   // [c][128 m-cols]  48 KB; reused for merge

    int b = blockIdx.y;
    int n0 = blockIdx.x * 64;
    int tid = threadIdx.x;
    int g   = tid >> 3;          // 0..31 row group
    int mc4 = (tid & 7) * 4;     // 0..28 col group (two float4 halves)
    int r0 = g * 2, r1 = r0 + 1;

    const float* xb = xn + (size_t)b * CC * NN;
    for (int t = tid; t < CC * 16; t += 256) {
        int c = t >> 4, q = (t & 15) * 4;
        *(float4*)&Xn_s[c * 64 + q] = *(const float4*)&xb[(size_t)c * NN + n0 + q];
    }
    __syncthreads();

    float2 sqn2 = *(const float2*)&sq[b * NN + n0 + r0];
    float sqn0 = sqn2.x, sqn1 = sqn2.y;

    float tv0[KK], tv1[KK]; int ti0[KK], ti1[KK];
    #pragma unroll
    for (int k = 0; k < KK; k++) { tv0[k] = 1e30f; tv1[k] = 1e30f; ti0[k] = 0; ti1[k] = 0; }

    for (int m0 = 0; m0 < NN; m0 += 128) {
        __syncthreads();
        if (m0 + 128 <= NN) {
            for (int t = tid; t < CC * 32; t += 256) {
                int c = t >> 5, q = (t & 31) * 4;
                *(float4*)&sh2[c * 128 + q] =
                    *(const float4*)&xb[(size_t)c * NN + m0 + q];
            }
        } else {
            for (int t = tid; t < CC * 16; t += 256) {
                int c = t >> 4, q = (t & 15) * 4;
                *(float4*)&sh2[c * 128 + q] =
                    *(const float4*)&xb[(size_t)c * NN + m0 + q];
            }
        }
        __syncthreads();
        #pragma unroll 1
        for (int h = 0; h < 2; h++) {
            int m0h = m0 + h * 64;
            if (m0h >= NN) break;
            const float* sb = sh2 + h * 64;
            ull acc0[4], acc1[4];
            #pragma unroll
            for (int j = 0; j < 4; j++) { acc0[j] = 0ull; acc1[j] = 0ull; }
            #pragma unroll 8
            for (int c = 0; c < CC; c++) {
                float2 a = *(const float2*)&Xn_s[c * 64 + r0];            // broadcast
                ulonglong2 blp = *(const ulonglong2*)&sb[c * 128 + mc4];  // free pairs
                ulonglong2 brp = *(const ulonglong2*)&sb[c * 128 + 32 + mc4];
                ull bp[4] = {blp.x, blp.y, brp.x, brp.y};
                ull a0 = pack2(a.x, a.x), a1 = pack2(a.y, a.y);
                #pragma unroll
                for (int j = 0; j < 4; j++) {
                    ffma2(acc0[j], a0, bp[j]);
                    ffma2(acc1[j], a1, bp[j]);
                }
            }
            // epilogue: dist + branchless topk insert (16B-aligned vector loads)
            const float* sqm = sq + b * NN + m0h;
            float4 sqL = *(const float4*)&sqm[mc4];
            float4 sqR = *(const float4*)&sqm[32 + mc4];
            float sv[8] = {sqL.x, sqL.y, sqL.z, sqL.w, sqR.x, sqR.y, sqR.z, sqR.w};
            const float* rpr0 = rp + (size_t)(n0 + r0) * NN + m0h;
            const float* rpr1 = rp + (size_t)(n0 + r1) * NN + m0h;
            float4 rp0L = *(const float4*)&rpr0[mc4];
            float4 rp0R = *(const float4*)&rpr0[32 + mc4];
            float4 rp1L = *(const float4*)&rpr1[mc4];
            float4 rp1R = *(const float4*)&rpr1[32 + mc4];
            float r0v[8] = {rp0L.x, rp0L.y, rp0L.z, rp0L.w,
                            rp0R.x, rp0R.y, rp0R.z, rp0R.w};
            float r1v[8] = {rp1L.x, rp1L.y, rp1L.z, rp1L.w,
                            rp1R.x, rp1R.y, rp1R.z, rp1R.w};
            float2 p00 = unpack2(acc0[0]), p01 = unpack2(acc0[1]);
            float2 p02 = unpack2(acc0[2]), p03 = unpack2(acc0[3]);
            float2 p10 = unpack2(acc1[0]), p11 = unpack2(acc1[1]);
            float2 p12 = unpack2(acc1[2]), p13 = unpack2(acc1[3]);
            float dot0[8] = {p00.x, p00.y, p01.x, p01.y, p02.x, p02.y, p03.x, p03.y};
            float dot1[8] = {p10.x, p10.y, p11.x, p11.y, p12.x, p12.y, p13.x, p13.y};
            #pragma unroll
            for (int j = 0; j < 8; j++) {
                int m = m0h + (j < 4 ? mc4 + j : 32 + mc4 + (j - 4));
                float d0 = fmaf(-2.f, dot0[j], sqn0 + sv[j] + r0v[j]);
                float d1 = fmaf(-2.f, dot1[j], sqn1 + sv[j] + r1v[j]);
                ins9(d0, m, tv0, ti0);
                ins9(d1, m, tv1, ti1);
            }
        }
    }

    // ---------- merge: 8 sorted partial lists per row, single pass ----------
    __syncthreads();
    float* cv = dsm;                        // [64][8][9] values (4608 f)
    int*   ci = (int*)(dsm + 64 * 8 * KK);  // [64][8][9] indices
    int cg = tid & 7;
    #pragma unroll
    for (int k = 0; k < KK; k++) {
        cv[(r0 * 8 + cg) * KK + k] = tv0[k]; ci[(r0 * 8 + cg) * KK + k] = ti0[k];
        cv[(r1 * 8 + cg) * KK + k] = tv1[k]; ci[(r1 * 8 + cg) * KK + k] = ti1[k];
    }
    __syncthreads();
    if (tid < 64) {
        float* rv = cv + tid * 8 * KK;
        int*   ri = ci + tid * 8 * KK;
        int* op = oidx + ((size_t)b * NN + n0 + tid) * KK;
        for (int k = 0; k < KK; k++) {
            float best = 2e30f; int bi = 0, bt = 0;
            for (int t = 0; t < 8 * KK; t++) {
                float v = rv[t];
                if (v < best) { best = v; bi = ri[t]; bt = t; }
            }
            rv[bt] = 3e30f;   // consume
            op[k] = bi;
        }
    }
}

// ---------------- gather neighbors, max(x_j - x_i), write channel-interleaved (B,2C,N)
__global__ __launch_bounds__(256) void aggregate_kernel(
    const float* __restrict__ xf, const int* __restrict__ idx, float* __restrict__ y)
{
    int bc = blockIdx.x;            // b*CC + c
    __shared__ float row[NN];
    const float* p = xf + (size_t)bc * NN;
    for (int i = threadIdx.x; i < NN; i += 256) row[i] = p[i];
    __syncthreads();
    int b = bc / CC, c = bc - b * CC;
    const int* ip = idx + (size_t)b * NN * KK;
    float* y0 = y + ((size_t)b * C2 + 2 * c) * NN;
    float* y1 = y0 + NN;
    for (int n = threadIdx.x; n < NN; n += 256) {
        float xi = row[n];
        float mx = -3e38f;
        #pragma unroll
        for (int k = 0; k < KK; k++) {
            int j = ip[n * KK + k];
            mx = fmaxf(mx, row[j] - xi);
        }
        y0[n] = xi;
        y1[n] = mx;
    }
}

// ---------------- host orchestration ----------------
static constexpr int DIST_SMEM = CC * 192 * (int)sizeof(float);   // 73728 B

static void run_conv(const float* X, const float* W, const float* bias,
                     float* out, int Cout, int Cin)
{
    dim3 g(NN / 64, Cout / 96, BB);
    gemm_bias_kernel<<<g, 128, CONV_SMEM>>>(X, W, bias, out, Cout, Cin);
}
static void run_inorm(const float* in, float* out, const float* res, int Crows, int act)
{
    inorm_kernel<<<BB * Crows, 256>>>(in, out, res, act);
}

extern "C" void kernel_launch(void* const* d_in, const int* in_sizes, int n_in,
                              void* d_out, int out_size)
{
    (void)in_sizes; (void)n_in; (void)out_size;
    const float* x  = (const float*)d_in[0];
    const float* rp = (const float*)d_in[1];
    const float* P[20];
    for (int i = 0; i < 20; i++) P[i] = (const float*)d_in[2 + i];

    cudaFuncSetAttribute(dist_topk_kernel,
                         cudaFuncAttributeMaxDynamicSharedMemorySize, DIST_SMEM);
    cudaFuncSetAttribute(gemm_bias_kernel,
                         cudaFuncAttributeMaxDynamicSharedMemorySize, CONV_SMEM);

    float *act, *t1, *xf, *xnp, *sqp, *big; int* idxp;
    cudaGetSymbolAddress((void**)&act,  g_act);
    cudaGetSymbolAddress((void**)&t1,   g_t1);
    cudaGetSymbolAddress((void**)&xf,   g_xf);
    cudaGetSymbolAddress((void**)&xnp,  g_xn);
    cudaGetSymbolAddress((void**)&sqp,  g_sq);
    cudaGetSymbolAddress((void**)&idxp, g_idx);
    cudaGetSymbolAddress((void**)&big,  g_big);
    float* y2 = big;                          // (B,2C,N)
    float* t3 = big + (size_t)BB * C2 * NN;   // (B,2C,N)
    float* out = (float*)d_out;

    auto grapher = [&](const float* inx,
                       const float* w1, const float* b1,
                       const float* mw, const float* mb,
                       const float* w2, const float* b2, float* outp) {
        run_conv(inx, w1, b1, t1, CC, CC);
        run_inorm(t1, xf, nullptr, CC, 0);                          // xf
        l2norm_kernel<<<(BB * NN + 255) / 256, 256>>>(xf, xnp, sqp);
        dim3 dg(NN / 64, BB);
        dist_topk_kernel<<<dg, 256, DIST_SMEM>>>(xnp, sqp, rp, idxp);
        aggregate_kernel<<<BB * CC, 256>>>(xf, idxp, y2);           // (B,2C,N)
        run_conv(y2, mw, mb, t3, C2, C2);
        run_inorm(t3, t3, nullptr, C2, 1);                          // gelu, in-place
        run_conv(t3, w2, b2, t1, CC, C2);
        run_inorm(t1, outp, inx, CC, 0);                            // + shortcut
    };
    auto ffn = [&](float* a, const float* w1, const float* b1,
                   const float* w2, const float* b2) {
        run_conv(a, w1, b1, big, C4, CC);
        run_inorm(big, big, nullptr, C4, 1);                        // gelu, in-place
        run_conv(big, w2, b2, t1, CC, C4);
        run_inorm(t1, a, a, CC, 0);                                 // + shortcut
    };

    grapher(x, P[0], P[1], P[2], P[3], P[4], P[5], act);
    ffn(act, P[12], P[13], P[14], P[15]);
    run_inorm(act, act, nullptr, CC, 2);                            // relu(inorm)
    grapher(act, P[6], P[7], P[8], P[9], P[10], P[11], act);
    ffn(act, P[16], P[17], P[18], P[19]);
    run_inorm(act, out, x, CC, 0);                                  // x + inorm(y)
}